// round 1
// baseline (speedup 1.0000x reference)
#include <cuda_runtime.h>
#include <math.h>

#define N_NODES 50000
#define N_EDGES 800000
#define H1 128
#define F_NODE 1363
#define F_STRUCT 83
#define F_ESM 1280
#define EDGE_IN 258
#define NODE_IN 339
#define NLAYERS 4

// ---------------- scratch (static device globals; no allocs) ----------------
__device__ float g_h[N_NODES * H1];
__device__ float g_agg[N_NODES * H1];
__device__ float g_tmp[N_NODES * H1];
__device__ float g_nodein[N_NODES * NODE_IN];
__device__ float g_esm1[N_NODES * 256];
__device__ float g_cat[N_NODES * 192];
__device__ float g_last[N_NODES * 192];
__device__ float g_radial[N_EDGES];

__device__ __forceinline__ float siluf(float x) { return x / (1.f + expf(-x)); }
__device__ __forceinline__ float sigmf(float x) { return 1.f / (1.f + expf(-x)); }

// ---------------- radial = ||coords[row]-coords[col]||^2 ----------------
__global__ void radial_kernel(const float* __restrict__ coords,
                              const int* __restrict__ ei,
                              float* __restrict__ radial) {
    int e = blockIdx.x * blockDim.x + threadIdx.x;
    if (e >= N_EDGES) return;
    int r = ei[e], c = ei[N_EDGES + e];
    float dx = coords[r * 3 + 0] - coords[c * 3 + 0];
    float dy = coords[r * 3 + 1] - coords[c * 3 + 1];
    float dz = coords[r * 3 + 2] - coords[c * 3 + 2];
    radial[e] = dx * dx + dy * dy + dz * dz;
}

// ---------------- generic GEMM: Y = act(X @ W + b) [+Y]  ----------------
// block: 256 threads, 32 rows x 128 cols (grid.y selects col-block), 4x4/thread
#define KC 64
template <int ACT, bool RESID>
__global__ void gemm_act(const float* __restrict__ X, int ldx,
                         const float* __restrict__ W, const float* __restrict__ B,
                         float* __restrict__ Y, int ldy,
                         int M, int K, int CO) {
    __shared__ float As[32][KC];
    int t = threadIdx.x;
    int m0 = blockIdx.x * 32;
    int c0 = blockIdx.y * 128 + (t & 31) * 4;
    int rg = (t >> 5) * 4;
    float acc[4][4] = {};

    for (int k0 = 0; k0 < K; k0 += KC) {
        int kmax = min(KC, K - k0);
        __syncthreads();
        for (int idx = t; idx < 32 * KC; idx += 256) {
            int r = idx / KC, kk = idx % KC;
            float v = 0.f;
            if (m0 + r < M && kk < kmax) v = X[(size_t)(m0 + r) * ldx + k0 + kk];
            As[r][kk] = v;
        }
        __syncthreads();
        for (int kk = 0; kk < kmax; kk++) {
            float w0, w1, w2, w3;
            const float* wp = W + (size_t)(k0 + kk) * CO + c0;
            if (c0 + 3 < CO) {
                float4 w4 = *(const float4*)wp;
                w0 = w4.x; w1 = w4.y; w2 = w4.z; w3 = w4.w;
            } else {
                w0 = (c0 + 0 < CO) ? wp[0] : 0.f;
                w1 = (c0 + 1 < CO) ? wp[1] : 0.f;
                w2 = (c0 + 2 < CO) ? wp[2] : 0.f;
                w3 = (c0 + 3 < CO) ? wp[3] : 0.f;
            }
            float a0 = As[rg + 0][kk], a1 = As[rg + 1][kk];
            float a2 = As[rg + 2][kk], a3 = As[rg + 3][kk];
            acc[0][0] += a0 * w0; acc[0][1] += a0 * w1; acc[0][2] += a0 * w2; acc[0][3] += a0 * w3;
            acc[1][0] += a1 * w0; acc[1][1] += a1 * w1; acc[1][2] += a1 * w2; acc[1][3] += a1 * w3;
            acc[2][0] += a2 * w0; acc[2][1] += a2 * w1; acc[2][2] += a2 * w2; acc[2][3] += a2 * w3;
            acc[3][0] += a3 * w0; acc[3][1] += a3 * w1; acc[3][2] += a3 * w2; acc[3][3] += a3 * w3;
        }
    }
#pragma unroll
    for (int i = 0; i < 4; i++) {
        int m = m0 + rg + i;
        if (m >= M) continue;
#pragma unroll
        for (int j = 0; j < 4; j++) {
            int c = c0 + j;
            if (c >= CO) continue;
            float v = acc[i][j] + B[c];
            if (ACT == 1) v = siluf(v);
            if (ACT == 2) v = fmaxf(v, 0.f);
            if (RESID) v += Y[(size_t)m * ldy + c];
            Y[(size_t)m * ldy + c] = v;
        }
    }
}

// ---------------- fused edge layer ----------------
// 16 edges per block, 128 threads. Gather edge_in -> MLP(258->128->128) with
// silu -> attention gate -> atomic scatter-add into agg[row].
#define TILE_E 16
__global__ void edge_kernel(const float* __restrict__ h,
                            const float* __restrict__ radial,
                            const float* __restrict__ ea,
                            const int* __restrict__ ei,
                            const float* __restrict__ W1, const float* __restrict__ B1,
                            const float* __restrict__ W2, const float* __restrict__ B2,
                            const float* __restrict__ attw, const float* __restrict__ attb,
                            float* __restrict__ agg) {
    __shared__ float ein[TILE_E][260];
    __shared__ float hid[TILE_E][128];
    __shared__ float gate[TILE_E];
    __shared__ int rows_s[TILE_E];
    __shared__ int cols_s[TILE_E];

    int t = threadIdx.x;
    int e0 = blockIdx.x * TILE_E;
    if (t < TILE_E) rows_s[t] = ei[e0 + t];
    else if (t < 2 * TILE_E) cols_s[t - TILE_E] = ei[N_EDGES + e0 + (t - TILE_E)];
    __syncthreads();

    // stage edge_in = [h[row], h[col], radial, ea]
    for (int idx = t; idx < TILE_E * EDGE_IN; idx += 128) {
        int e = idx / EDGE_IN, k = idx % EDGE_IN;
        float v;
        if (k < 128)      v = h[(size_t)rows_s[e] * 128 + k];
        else if (k < 256) v = h[(size_t)cols_s[e] * 128 + (k - 128)];
        else if (k == 256) v = radial[e0 + e];
        else               v = ea[e0 + e];
        ein[e][k] = v;
    }
    __syncthreads();

    int eg = (t >> 5) * 4;       // edge base (0,4,8,12)
    int cg = (t & 31) * 4;       // col base
    // GEMM1: 258 -> 128, silu
    {
        float acc[4][4] = {};
#pragma unroll 2
        for (int k = 0; k < EDGE_IN; k++) {
            float4 w = *(const float4*)(W1 + (size_t)k * 128 + cg);
            float a0 = ein[eg + 0][k], a1 = ein[eg + 1][k];
            float a2 = ein[eg + 2][k], a3 = ein[eg + 3][k];
            acc[0][0] += a0 * w.x; acc[0][1] += a0 * w.y; acc[0][2] += a0 * w.z; acc[0][3] += a0 * w.w;
            acc[1][0] += a1 * w.x; acc[1][1] += a1 * w.y; acc[1][2] += a1 * w.z; acc[1][3] += a1 * w.w;
            acc[2][0] += a2 * w.x; acc[2][1] += a2 * w.y; acc[2][2] += a2 * w.z; acc[2][3] += a2 * w.w;
            acc[3][0] += a3 * w.x; acc[3][1] += a3 * w.y; acc[3][2] += a3 * w.z; acc[3][3] += a3 * w.w;
        }
        float b0 = B1[cg], b1 = B1[cg + 1], b2 = B1[cg + 2], b3 = B1[cg + 3];
#pragma unroll
        for (int i = 0; i < 4; i++) {
            hid[eg + i][cg + 0] = siluf(acc[i][0] + b0);
            hid[eg + i][cg + 1] = siluf(acc[i][1] + b1);
            hid[eg + i][cg + 2] = siluf(acc[i][2] + b2);
            hid[eg + i][cg + 3] = siluf(acc[i][3] + b3);
        }
    }
    __syncthreads();

    // GEMM2: 128 -> 128, silu -> m (written back into hid after sync)
    float m[4][4];
    {
        float acc[4][4] = {};
#pragma unroll 2
        for (int k = 0; k < 128; k++) {
            float4 w = *(const float4*)(W2 + (size_t)k * 128 + cg);
            float a0 = hid[eg + 0][k], a1 = hid[eg + 1][k];
            float a2 = hid[eg + 2][k], a3 = hid[eg + 3][k];
            acc[0][0] += a0 * w.x; acc[0][1] += a0 * w.y; acc[0][2] += a0 * w.z; acc[0][3] += a0 * w.w;
            acc[1][0] += a1 * w.x; acc[1][1] += a1 * w.y; acc[1][2] += a1 * w.z; acc[1][3] += a1 * w.w;
            acc[2][0] += a2 * w.x; acc[2][1] += a2 * w.y; acc[2][2] += a2 * w.z; acc[2][3] += a2 * w.w;
            acc[3][0] += a3 * w.x; acc[3][1] += a3 * w.y; acc[3][2] += a3 * w.z; acc[3][3] += a3 * w.w;
        }
        float b0 = B2[cg], b1 = B2[cg + 1], b2 = B2[cg + 2], b3 = B2[cg + 3];
#pragma unroll
        for (int i = 0; i < 4; i++) {
            m[i][0] = siluf(acc[i][0] + b0);
            m[i][1] = siluf(acc[i][1] + b1);
            m[i][2] = siluf(acc[i][2] + b2);
            m[i][3] = siluf(acc[i][3] + b3);
        }
    }
    __syncthreads();   // all reads of hid done
#pragma unroll
    for (int i = 0; i < 4; i++) {
        hid[eg + i][cg + 0] = m[i][0];
        hid[eg + i][cg + 1] = m[i][1];
        hid[eg + i][cg + 2] = m[i][2];
        hid[eg + i][cg + 3] = m[i][3];
    }
    __syncthreads();

    // attention gate: gate[e] = sigmoid(m[e] . attw + attb)
    {
        int e = t >> 3, l8 = t & 7;
        float s = 0.f;
        for (int c = l8; c < 128; c += 8) s += hid[e][c] * attw[c];
        s += __shfl_down_sync(0xffffffffu, s, 4, 8);
        s += __shfl_down_sync(0xffffffffu, s, 2, 8);
        s += __shfl_down_sync(0xffffffffu, s, 1, 8);
        if (l8 == 0) gate[e] = sigmf(s + attb[0]);
    }
    __syncthreads();

    // scatter: agg[row[e]] += m[e] * gate[e]
    for (int idx = t; idx < TILE_E * 128; idx += 128) {
        int e = idx >> 7, c = idx & 127;
        atomicAdd(agg + (size_t)rows_s[e] * 128 + c, hid[e][c] * gate[e]);
    }
}

// ---------------- node_in = [h, agg, h0] ----------------
__global__ void concat_node(const float* __restrict__ h, const float* __restrict__ agg,
                            const float* __restrict__ na, float* __restrict__ out) {
    int idx = blockIdx.x * blockDim.x + threadIdx.x;
    if (idx >= N_NODES * NODE_IN) return;
    int n = idx / NODE_IN, k = idx % NODE_IN;
    float v;
    if (k < 128)      v = h[(size_t)n * 128 + k];
    else if (k < 256) v = agg[(size_t)n * 128 + (k - 128)];
    else              v = na[(size_t)n * F_NODE + (k - 256)];
    out[idx] = v;
}

// ---------------- final head: out = sigmoid(X @ w + b), K=192, CO=1 ----------------
__global__ void last2_kernel(const float* __restrict__ X, const float* __restrict__ w,
                             const float* __restrict__ b, float* __restrict__ out) {
    int gt = blockIdx.x * blockDim.x + threadIdx.x;
    int n = gt >> 5, lane = gt & 31;
    if (n >= N_NODES) return;
    float s = 0.f;
    for (int c = lane; c < 192; c += 32) s += X[(size_t)n * 192 + c] * w[c];
#pragma unroll
    for (int o = 16; o; o >>= 1) s += __shfl_down_sync(0xffffffffu, s, o);
    if (lane == 0) out[n] = sigmf(s + b[0]);
}

// ---------------- launch ----------------
extern "C" void kernel_launch(void* const* d_in, const int* in_sizes, int n_in,
                              void* d_out, int out_size) {
    const float* node_attrs = (const float*)d_in[0];
    const float* coords     = (const float*)d_in[1];
    const int*   ei         = (const int*)d_in[2];
    const float* ea         = (const float*)d_in[3];
    const float* emb_w  = (const float*)d_in[4];
    const float* emb_b  = (const float*)d_in[5];
    const float* edge_w1 = (const float*)d_in[6];
    const float* edge_b1 = (const float*)d_in[7];
    const float* edge_w2 = (const float*)d_in[8];
    const float* edge_b2 = (const float*)d_in[9];
    const float* att_w   = (const float*)d_in[10];
    const float* att_b   = (const float*)d_in[11];
    const float* node_w1 = (const float*)d_in[12];
    const float* node_b1 = (const float*)d_in[13];
    const float* node_w2 = (const float*)d_in[14];
    const float* node_b2 = (const float*)d_in[15];
    const float* dec_w1  = (const float*)d_in[16];
    const float* dec_b1  = (const float*)d_in[17];
    const float* dec_w2  = (const float*)d_in[18];
    const float* dec_b2  = (const float*)d_in[19];
    const float* ffnn_w1 = (const float*)d_in[20];
    const float* ffnn_b1 = (const float*)d_in[21];
    const float* ffnn_w2 = (const float*)d_in[22];
    const float* ffnn_b2 = (const float*)d_in[23];
    const float* last_w1 = (const float*)d_in[24];
    const float* last_b1 = (const float*)d_in[25];
    const float* last_w2 = (const float*)d_in[26];
    const float* last_b2 = (const float*)d_in[27];

    float *h, *agg, *tmp, *nodein, *esm1, *cat, *last, *radial;
    cudaGetSymbolAddress((void**)&h, g_h);
    cudaGetSymbolAddress((void**)&agg, g_agg);
    cudaGetSymbolAddress((void**)&tmp, g_tmp);
    cudaGetSymbolAddress((void**)&nodein, g_nodein);
    cudaGetSymbolAddress((void**)&esm1, g_esm1);
    cudaGetSymbolAddress((void**)&cat, g_cat);
    cudaGetSymbolAddress((void**)&last, g_last);
    cudaGetSymbolAddress((void**)&radial, g_radial);

    const int GB = (N_NODES + 31) / 32;

    radial_kernel<<<(N_EDGES + 255) / 256, 256>>>(coords, ei, radial);

    // h = h0 @ emb_w + emb_b
    gemm_act<0, false><<<dim3(GB, 1), 256>>>(node_attrs, F_NODE, emb_w, emb_b,
                                             h, 128, N_NODES, F_STRUCT, 128);
    // ESM branch (independent): writes cat[:,128:192]
    gemm_act<2, false><<<dim3(GB, 2), 256>>>(node_attrs + F_STRUCT, F_NODE, ffnn_w1, ffnn_b1,
                                             esm1, 256, N_NODES, F_ESM, 256);
    gemm_act<2, false><<<dim3(GB, 1), 256>>>(esm1, 256, ffnn_w2, ffnn_b2,
                                             cat + 128, 192, N_NODES, 256, 64);

    for (int i = 0; i < NLAYERS; i++) {
        cudaMemsetAsync(agg, 0, (size_t)N_NODES * 128 * sizeof(float));
        edge_kernel<<<N_EDGES / TILE_E, 128>>>(h, radial, ea, ei,
                                               edge_w1 + (size_t)i * EDGE_IN * 128,
                                               edge_b1 + (size_t)i * 128,
                                               edge_w2 + (size_t)i * 128 * 128,
                                               edge_b2 + (size_t)i * 128,
                                               att_w + (size_t)i * 128,
                                               att_b + i, agg);
        concat_node<<<(N_NODES * NODE_IN + 255) / 256, 256>>>(h, agg, node_attrs, nodein);
        gemm_act<1, false><<<dim3(GB, 1), 256>>>(nodein, NODE_IN,
                                                 node_w1 + (size_t)i * NODE_IN * 128,
                                                 node_b1 + (size_t)i * 128,
                                                 tmp, 128, N_NODES, NODE_IN, 128);
        gemm_act<0, true><<<dim3(GB, 1), 256>>>(tmp, 128,
                                                node_w2 + (size_t)i * 128 * 128,
                                                node_b2 + (size_t)i * 128,
                                                h, 128, N_NODES, 128, 128);
    }

    // decoder -> cat[:,0:128]
    gemm_act<1, false><<<dim3(GB, 1), 256>>>(h, 128, dec_w1, dec_b1, tmp, 128, N_NODES, 128, 128);
    gemm_act<0, false><<<dim3(GB, 1), 256>>>(tmp, 128, dec_w2, dec_b2, cat, 192, N_NODES, 128, 128);

    // final head
    gemm_act<1, false><<<dim3(GB, 2), 256>>>(cat, 192, last_w1, last_b1, last, 192, N_NODES, 192, 192);
    last2_kernel<<<(N_NODES * 32 + 255) / 256, 256>>>(last, last_w2, last_b2, (float*)d_out);
}

// round 2
// speedup vs baseline: 1.6423x; 1.6423x over previous
#include <cuda_runtime.h>
#include <math.h>

#define N_NODES 50000
#define N_EDGES 800000
#define H1 128
#define F_NODE 1363
#define F_STRUCT 83
#define F_ESM 1280
#define EDGE_IN 258
#define NODE_IN 339
#define NLAYERS 4

// ---------------- scratch (static device globals; no allocs) ----------------
__device__ float g_h[N_NODES * H1];
__device__ float g_P[N_NODES * H1];
__device__ float g_Q[N_NODES * H1];
__device__ float g_agg[N_NODES * H1];
__device__ float g_tmp[N_NODES * H1];
__device__ float g_nodein[N_NODES * NODE_IN];
__device__ float g_esm1[N_NODES * 256];
__device__ float g_cat[N_NODES * 192];
__device__ float g_last[N_NODES * 192];
__device__ float g_radial[N_EDGES];

__device__ __forceinline__ float siluf(float x) { return x / (1.f + __expf(-x)); }
__device__ __forceinline__ float sigmf(float x) { return 1.f / (1.f + __expf(-x)); }

// ---------------- radial = ||coords[row]-coords[col]||^2 ----------------
__global__ void radial_kernel(const float* __restrict__ coords,
                              const int* __restrict__ ei,
                              float* __restrict__ radial) {
    int e = blockIdx.x * blockDim.x + threadIdx.x;
    if (e >= N_EDGES) return;
    int r = ei[e], c = ei[N_EDGES + e];
    float dx = coords[r * 3 + 0] - coords[c * 3 + 0];
    float dy = coords[r * 3 + 1] - coords[c * 3 + 1];
    float dz = coords[r * 3 + 2] - coords[c * 3 + 2];
    radial[e] = dx * dx + dy * dy + dz * dz;
}

// ---------------- generic GEMM: Y = act(X @ W [+ b]) [+Y]  ----------------
// block: 256 threads, 32 rows x 128 cols (grid.y selects col-block), 4x4/thread
#define KC 64
template <int ACT, bool RESID, bool BIAS>
__global__ void gemm_act(const float* __restrict__ X, int ldx,
                         const float* __restrict__ W, const float* __restrict__ B,
                         float* __restrict__ Y, int ldy,
                         int M, int K, int CO) {
    __shared__ float As[32][KC];
    int t = threadIdx.x;
    int m0 = blockIdx.x * 32;
    int c0 = blockIdx.y * 128 + (t & 31) * 4;
    int rg = (t >> 5) * 4;
    float acc[4][4] = {};

    for (int k0 = 0; k0 < K; k0 += KC) {
        int kmax = min(KC, K - k0);
        __syncthreads();
        for (int idx = t; idx < 32 * KC; idx += 256) {
            int r = idx / KC, kk = idx % KC;
            float v = 0.f;
            if (m0 + r < M && kk < kmax) v = X[(size_t)(m0 + r) * ldx + k0 + kk];
            As[r][kk] = v;
        }
        __syncthreads();
        for (int kk = 0; kk < kmax; kk++) {
            float w0, w1, w2, w3;
            const float* wp = W + (size_t)(k0 + kk) * CO + c0;
            if (c0 + 3 < CO) {
                float4 w4 = *(const float4*)wp;
                w0 = w4.x; w1 = w4.y; w2 = w4.z; w3 = w4.w;
            } else {
                w0 = (c0 + 0 < CO) ? wp[0] : 0.f;
                w1 = (c0 + 1 < CO) ? wp[1] : 0.f;
                w2 = (c0 + 2 < CO) ? wp[2] : 0.f;
                w3 = (c0 + 3 < CO) ? wp[3] : 0.f;
            }
            float a0 = As[rg + 0][kk], a1 = As[rg + 1][kk];
            float a2 = As[rg + 2][kk], a3 = As[rg + 3][kk];
            acc[0][0] += a0 * w0; acc[0][1] += a0 * w1; acc[0][2] += a0 * w2; acc[0][3] += a0 * w3;
            acc[1][0] += a1 * w0; acc[1][1] += a1 * w1; acc[1][2] += a1 * w2; acc[1][3] += a1 * w3;
            acc[2][0] += a2 * w0; acc[2][1] += a2 * w1; acc[2][2] += a2 * w2; acc[2][3] += a2 * w3;
            acc[3][0] += a3 * w0; acc[3][1] += a3 * w1; acc[3][2] += a3 * w2; acc[3][3] += a3 * w3;
        }
    }
#pragma unroll
    for (int i = 0; i < 4; i++) {
        int m = m0 + rg + i;
        if (m >= M) continue;
#pragma unroll
        for (int j = 0; j < 4; j++) {
            int c = c0 + j;
            if (c >= CO) continue;
            float v = acc[i][j];
            if (BIAS) v += B[c];
            if (ACT == 1) v = siluf(v);
            if (ACT == 2) v = fmaxf(v, 0.f);
            if (RESID) v += Y[(size_t)m * ldy + c];
            Y[(size_t)m * ldy + c] = v;
        }
    }
}

// ---------------- fused edge layer (decomposed GEMM1) ----------------
// hid = silu(P[row] + Q[col] + radial*wr + ea*we + b1)
// m   = silu(hid @ W2 + b2);  gate = sigmoid(m.attw + attb)
// agg[row] += m * gate
#define TILE_E 32
__global__ __launch_bounds__(256) void edge_kernel(
        const float* __restrict__ P, const float* __restrict__ Q,
        const float* __restrict__ radial, const float* __restrict__ ea,
        const int* __restrict__ ei,
        const float* __restrict__ wr, const float* __restrict__ we,
        const float* __restrict__ b1,
        const float* __restrict__ W2, const float* __restrict__ B2,
        const float* __restrict__ attw, const float* __restrict__ attb,
        float* __restrict__ agg) {
    __shared__ float hid[TILE_E][128];
    __shared__ float ms[TILE_E][128];
    __shared__ float gate[TILE_E];
    __shared__ int rows_s[TILE_E];
    __shared__ int cols_s[TILE_E];
    __shared__ float rad_s[TILE_E];
    __shared__ float eas[TILE_E];
    __shared__ float wr_s[128], we_s[128], b1_s[128], attw_s[128];

    int t = threadIdx.x;
    int e0 = blockIdx.x * TILE_E;
    if (t < TILE_E) {
        rows_s[t] = ei[e0 + t];
        rad_s[t] = radial[e0 + t];
        eas[t] = ea[e0 + t];
    } else if (t < 2 * TILE_E) {
        cols_s[t - TILE_E] = ei[N_EDGES + e0 + (t - TILE_E)];
    }
    for (int idx = t; idx < 512; idx += 256) {
        int a = idx >> 7, c = idx & 127;
        if (a == 0) wr_s[c] = wr[c];
        else if (a == 1) we_s[c] = we[c];
        else if (a == 2) b1_s[c] = b1[c];
        else attw_s[c] = attw[c];
    }
    __syncthreads();

    // stage hidden layer 1 directly (GEMM1 decomposed to node projections)
#pragma unroll
    for (int idx = t; idx < TILE_E * 128; idx += 256) {
        int e = idx >> 7, c = idx & 127;
        float v = P[(size_t)rows_s[e] * 128 + c] + Q[(size_t)cols_s[e] * 128 + c]
                + rad_s[e] * wr_s[c] + eas[e] * we_s[c] + b1_s[c];
        hid[e][c] = siluf(v);
    }
    __syncthreads();

    int eg = (t >> 5) * 4;       // edge base (0..28)
    int cg = (t & 31) * 4;       // col base
    // GEMM2: 128 -> 128, silu
    {
        float acc[4][4] = {};
#pragma unroll 4
        for (int k = 0; k < 128; k++) {
            float4 w = *(const float4*)(W2 + (size_t)k * 128 + cg);
            float a0 = hid[eg + 0][k], a1 = hid[eg + 1][k];
            float a2 = hid[eg + 2][k], a3 = hid[eg + 3][k];
            acc[0][0] += a0 * w.x; acc[0][1] += a0 * w.y; acc[0][2] += a0 * w.z; acc[0][3] += a0 * w.w;
            acc[1][0] += a1 * w.x; acc[1][1] += a1 * w.y; acc[1][2] += a1 * w.z; acc[1][3] += a1 * w.w;
            acc[2][0] += a2 * w.x; acc[2][1] += a2 * w.y; acc[2][2] += a2 * w.z; acc[2][3] += a2 * w.w;
            acc[3][0] += a3 * w.x; acc[3][1] += a3 * w.y; acc[3][2] += a3 * w.z; acc[3][3] += a3 * w.w;
        }
        float b0 = B2[cg], b1v = B2[cg + 1], b2 = B2[cg + 2], b3 = B2[cg + 3];
#pragma unroll
        for (int i = 0; i < 4; i++) {
            ms[eg + i][cg + 0] = siluf(acc[i][0] + b0);
            ms[eg + i][cg + 1] = siluf(acc[i][1] + b1v);
            ms[eg + i][cg + 2] = siluf(acc[i][2] + b2);
            ms[eg + i][cg + 3] = siluf(acc[i][3] + b3);
        }
    }
    __syncthreads();

    // attention gate: gate[e] = sigmoid(m[e] . attw + attb)
    {
        int e = t >> 3, l8 = t & 7;
        float s = 0.f;
#pragma unroll
        for (int c = l8; c < 128; c += 8) s += ms[e][c] * attw_s[c];
        s += __shfl_down_sync(0xffffffffu, s, 4, 8);
        s += __shfl_down_sync(0xffffffffu, s, 2, 8);
        s += __shfl_down_sync(0xffffffffu, s, 1, 8);
        if (l8 == 0) gate[e] = sigmf(s + attb[0]);
    }
    __syncthreads();

    // scatter: agg[row[e]] += m[e] * gate[e]
#pragma unroll
    for (int idx = t; idx < TILE_E * 128; idx += 256) {
        int e = idx >> 7, c = idx & 127;
        atomicAdd(agg + (size_t)rows_s[e] * 128 + c, ms[e][c] * gate[e]);
    }
}

// ---------------- node_in = [h, agg, h0] ----------------
__global__ void concat_node(const float* __restrict__ h, const float* __restrict__ agg,
                            const float* __restrict__ na, float* __restrict__ out) {
    int idx = blockIdx.x * blockDim.x + threadIdx.x;
    if (idx >= N_NODES * NODE_IN) return;
    int n = idx / NODE_IN, k = idx % NODE_IN;
    float v;
    if (k < 128)      v = h[(size_t)n * 128 + k];
    else if (k < 256) v = agg[(size_t)n * 128 + (k - 128)];
    else              v = na[(size_t)n * F_NODE + (k - 256)];
    out[idx] = v;
}

// ---------------- final head: out = sigmoid(X @ w + b), K=192, CO=1 ----------------
__global__ void last2_kernel(const float* __restrict__ X, const float* __restrict__ w,
                             const float* __restrict__ b, float* __restrict__ out) {
    int gt = blockIdx.x * blockDim.x + threadIdx.x;
    int n = gt >> 5, lane = gt & 31;
    if (n >= N_NODES) return;
    float s = 0.f;
    for (int c = lane; c < 192; c += 32) s += X[(size_t)n * 192 + c] * w[c];
#pragma unroll
    for (int o = 16; o; o >>= 1) s += __shfl_down_sync(0xffffffffu, s, o);
    if (lane == 0) out[n] = sigmf(s + b[0]);
}

// ---------------- launch ----------------
extern "C" void kernel_launch(void* const* d_in, const int* in_sizes, int n_in,
                              void* d_out, int out_size) {
    const float* node_attrs = (const float*)d_in[0];
    const float* coords     = (const float*)d_in[1];
    const int*   ei         = (const int*)d_in[2];
    const float* ea         = (const float*)d_in[3];
    const float* emb_w  = (const float*)d_in[4];
    const float* emb_b  = (const float*)d_in[5];
    const float* edge_w1 = (const float*)d_in[6];
    const float* edge_b1 = (const float*)d_in[7];
    const float* edge_w2 = (const float*)d_in[8];
    const float* edge_b2 = (const float*)d_in[9];
    const float* att_w   = (const float*)d_in[10];
    const float* att_b   = (const float*)d_in[11];
    const float* node_w1 = (const float*)d_in[12];
    const float* node_b1 = (const float*)d_in[13];
    const float* node_w2 = (const float*)d_in[14];
    const float* node_b2 = (const float*)d_in[15];
    const float* dec_w1  = (const float*)d_in[16];
    const float* dec_b1  = (const float*)d_in[17];
    const float* dec_w2  = (const float*)d_in[18];
    const float* dec_b2  = (const float*)d_in[19];
    const float* ffnn_w1 = (const float*)d_in[20];
    const float* ffnn_b1 = (const float*)d_in[21];
    const float* ffnn_w2 = (const float*)d_in[22];
    const float* ffnn_b2 = (const float*)d_in[23];
    const float* last_w1 = (const float*)d_in[24];
    const float* last_b1 = (const float*)d_in[25];
    const float* last_w2 = (const float*)d_in[26];
    const float* last_b2 = (const float*)d_in[27];

    float *h, *P, *Q, *agg, *tmp, *nodein, *esm1, *cat, *last, *radial;
    cudaGetSymbolAddress((void**)&h, g_h);
    cudaGetSymbolAddress((void**)&P, g_P);
    cudaGetSymbolAddress((void**)&Q, g_Q);
    cudaGetSymbolAddress((void**)&agg, g_agg);
    cudaGetSymbolAddress((void**)&tmp, g_tmp);
    cudaGetSymbolAddress((void**)&nodein, g_nodein);
    cudaGetSymbolAddress((void**)&esm1, g_esm1);
    cudaGetSymbolAddress((void**)&cat, g_cat);
    cudaGetSymbolAddress((void**)&last, g_last);
    cudaGetSymbolAddress((void**)&radial, g_radial);

    const int GB = (N_NODES + 31) / 32;

    radial_kernel<<<(N_EDGES + 255) / 256, 256>>>(coords, ei, radial);

    // h = h0 @ emb_w + emb_b
    gemm_act<0, false, true><<<dim3(GB, 1), 256>>>(node_attrs, F_NODE, emb_w, emb_b,
                                                   h, 128, N_NODES, F_STRUCT, 128);
    // ESM branch (independent): writes cat[:,128:192]
    gemm_act<2, false, true><<<dim3(GB, 2), 256>>>(node_attrs + F_STRUCT, F_NODE, ffnn_w1, ffnn_b1,
                                                   esm1, 256, N_NODES, F_ESM, 256);
    gemm_act<2, false, true><<<dim3(GB, 1), 256>>>(esm1, 256, ffnn_w2, ffnn_b2,
                                                   cat + 128, 192, N_NODES, 256, 64);

    for (int i = 0; i < NLAYERS; i++) {
        const float* W1 = edge_w1 + (size_t)i * EDGE_IN * 128;
        // P = h @ W1[0:128], Q = h @ W1[128:256]  (exact GEMM1 decomposition)
        gemm_act<0, false, false><<<dim3(GB, 1), 256>>>(h, 128, W1, nullptr,
                                                        P, 128, N_NODES, 128, 128);
        gemm_act<0, false, false><<<dim3(GB, 1), 256>>>(h, 128, W1 + 128 * 128, nullptr,
                                                        Q, 128, N_NODES, 128, 128);
        cudaMemsetAsync(agg, 0, (size_t)N_NODES * 128 * sizeof(float));
        edge_kernel<<<N_EDGES / TILE_E, 256>>>(P, Q, radial, ea, ei,
                                               W1 + 256 * 128,          // wr
                                               W1 + 257 * 128,          // we
                                               edge_b1 + (size_t)i * 128,
                                               edge_w2 + (size_t)i * 128 * 128,
                                               edge_b2 + (size_t)i * 128,
                                               att_w + (size_t)i * 128,
                                               att_b + i, agg);
        concat_node<<<(N_NODES * NODE_IN + 255) / 256, 256>>>(h, agg, node_attrs, nodein);
        gemm_act<1, false, true><<<dim3(GB, 1), 256>>>(nodein, NODE_IN,
                                                       node_w1 + (size_t)i * NODE_IN * 128,
                                                       node_b1 + (size_t)i * 128,
                                                       tmp, 128, N_NODES, NODE_IN, 128);
        gemm_act<0, true, true><<<dim3(GB, 1), 256>>>(tmp, 128,
                                                      node_w2 + (size_t)i * 128 * 128,
                                                      node_b2 + (size_t)i * 128,
                                                      h, 128, N_NODES, 128, 128);
    }

    // decoder -> cat[:,0:128]
    gemm_act<1, false, true><<<dim3(GB, 1), 256>>>(h, 128, dec_w1, dec_b1, tmp, 128, N_NODES, 128, 128);
    gemm_act<0, false, true><<<dim3(GB, 1), 256>>>(tmp, 128, dec_w2, dec_b2, cat, 192, N_NODES, 128, 128);

    // final head
    gemm_act<1, false, true><<<dim3(GB, 2), 256>>>(cat, 192, last_w1, last_b1, last, 192, N_NODES, 192, 192);
    last2_kernel<<<(N_NODES * 32 + 255) / 256, 256>>>(last, last_w2, last_b2, (float*)d_out);
}

// round 3
// speedup vs baseline: 2.1915x; 1.3344x over previous
#include <cuda_runtime.h>
#include <math.h>
#include <stdint.h>

#define N_NODES 50000
#define N_EDGES 800000
#define H1 128
#define F_NODE 1363
#define F_STRUCT 83
#define F_ESM 1280
#define EDGE_IN 258
#define NODE_IN 339
#define NLAYERS 4

// ---------------- scratch (static device globals; no allocs) ----------------
__device__ float g_h[N_NODES * H1];
__device__ float g_P[N_NODES * H1];
__device__ float g_Q[N_NODES * H1];
__device__ float g_agg[N_NODES * H1];
__device__ float g_tmp[N_NODES * H1];
__device__ float g_nodein[N_NODES * NODE_IN];
__device__ float g_esm1[N_NODES * 256];
__device__ float g_cat[N_NODES * 192];
__device__ float g_last[N_NODES * 192];
__device__ float g_radial[N_EDGES];

__device__ __forceinline__ float siluf(float x) { return x / (1.f + __expf(-x)); }
__device__ __forceinline__ float sigmf(float x) { return 1.f / (1.f + __expf(-x)); }
__device__ __forceinline__ uint32_t tf32r(float x) {
    uint32_t r; asm("cvt.rna.tf32.f32 %0, %1;" : "=r"(r) : "f"(x)); return r;
}

// ---------------- radial = ||coords[row]-coords[col]||^2 ----------------
__global__ void radial_kernel(const float* __restrict__ coords,
                              const int* __restrict__ ei,
                              float* __restrict__ radial) {
    int e = blockIdx.x * blockDim.x + threadIdx.x;
    if (e >= N_EDGES) return;
    int r = ei[e], c = ei[N_EDGES + e];
    float dx = coords[r * 3 + 0] - coords[c * 3 + 0];
    float dy = coords[r * 3 + 1] - coords[c * 3 + 1];
    float dz = coords[r * 3 + 2] - coords[c * 3 + 2];
    radial[e] = dx * dx + dy * dy + dz * dz;
}

// ---------------- generic GEMM: Y = act(X @ W [+ b]) [+Y]  ----------------
// 256 threads, 32 rows x 128 cols per block; BOTH operands staged in smem.
#define KC 32
template <int ACT, bool RESID, bool BIAS>
__global__ __launch_bounds__(256) void gemm_act(
        const float* __restrict__ X, int ldx,
        const float* __restrict__ W, const float* __restrict__ B,
        float* __restrict__ Y, int ldy,
        int M, int K, int CO) {
    __shared__ float As[32][KC];
    __shared__ float Ws[KC][128];
    int t = threadIdx.x;
    int m0 = blockIdx.x * 32;
    int cb = blockIdx.y * 128;
    int c0 = cb + (t & 31) * 4;
    int rg = (t >> 5) * 4;
    float acc[4][4] = {};

    for (int k0 = 0; k0 < K; k0 += KC) {
        __syncthreads();
        for (int idx = t; idx < 32 * KC; idx += 256) {
            int r = idx / KC, kk = idx % KC;
            float v = 0.f;
            if (m0 + r < M && k0 + kk < K) v = X[(size_t)(m0 + r) * ldx + k0 + kk];
            As[r][kk] = v;
        }
        for (int idx = t; idx < KC * 32; idx += 256) {
            int kk = idx >> 5, c4 = (idx & 31) * 4;
            float4 v = {0.f, 0.f, 0.f, 0.f};
            if (k0 + kk < K) {
                const float* wp = W + (size_t)(k0 + kk) * CO + cb + c4;
                if (cb + c4 + 3 < CO) v = *(const float4*)wp;
                else {
                    if (cb + c4 + 0 < CO) v.x = wp[0];
                    if (cb + c4 + 1 < CO) v.y = wp[1];
                    if (cb + c4 + 2 < CO) v.z = wp[2];
                    if (cb + c4 + 3 < CO) v.w = wp[3];
                }
            }
            *(float4*)&Ws[kk][c4] = v;
        }
        __syncthreads();
#pragma unroll
        for (int kk = 0; kk < KC; kk++) {
            float4 w = *(const float4*)&Ws[kk][(t & 31) * 4];
            float a0 = As[rg + 0][kk], a1 = As[rg + 1][kk];
            float a2 = As[rg + 2][kk], a3 = As[rg + 3][kk];
            acc[0][0] += a0 * w.x; acc[0][1] += a0 * w.y; acc[0][2] += a0 * w.z; acc[0][3] += a0 * w.w;
            acc[1][0] += a1 * w.x; acc[1][1] += a1 * w.y; acc[1][2] += a1 * w.z; acc[1][3] += a1 * w.w;
            acc[2][0] += a2 * w.x; acc[2][1] += a2 * w.y; acc[2][2] += a2 * w.z; acc[2][3] += a2 * w.w;
            acc[3][0] += a3 * w.x; acc[3][1] += a3 * w.y; acc[3][2] += a3 * w.z; acc[3][3] += a3 * w.w;
        }
    }
#pragma unroll
    for (int i = 0; i < 4; i++) {
        int m = m0 + rg + i;
        if (m >= M) continue;
#pragma unroll
        for (int j = 0; j < 4; j++) {
            int c = c0 + j;
            if (c >= CO) continue;
            float v = acc[i][j];
            if (BIAS) v += B[c];
            if (ACT == 1) v = siluf(v);
            if (ACT == 2) v = fmaxf(v, 0.f);
            if (RESID) v += Y[(size_t)m * ldy + c];
            Y[(size_t)m * ldy + c] = v;
        }
    }
}

// ---------------- fused edge layer: tf32 tensor-core GEMM2 ----------------
// hid = silu(P[row]+Q[col]+radial*wr+ea*we+b1)   (tf32-rounded into smem)
// m   = silu(hid @ W2 + b2)  via mma.m16n8k4.tf32
// gate = sigmoid(m.attw+attb);  agg[row] += m*gate
#define TILE_E 64
// smem float offsets
#define OFF_W2S   0                    // [128][136]
#define OFF_HID   (128*136)            // [64][132]
#define OFF_WR    (OFF_HID + 64*132)
#define OFF_WE    (OFF_WR + 128)
#define OFF_B1    (OFF_WE + 128)
#define OFF_ATT   (OFF_B1 + 128)
#define OFF_B2    (OFF_ATT + 128)
#define OFF_RAD   (OFF_B2 + 128)
#define OFF_EA    (OFF_RAD + 64)
#define OFF_GATE  (OFF_EA + 64)
#define OFF_ROWS  (OFF_GATE + 64)
#define OFF_COLS  (OFF_ROWS + 64)
#define EDGE_SMEM ((OFF_COLS + 64) * 4)

__global__ __launch_bounds__(256) void edge_kernel(
        const float* __restrict__ P, const float* __restrict__ Q,
        const float* __restrict__ radial, const float* __restrict__ ea,
        const int* __restrict__ ei,
        const float* __restrict__ wr, const float* __restrict__ we,
        const float* __restrict__ b1,
        const float* __restrict__ W2, const float* __restrict__ B2,
        const float* __restrict__ attw, const float* __restrict__ attb,
        float* __restrict__ agg) {
    extern __shared__ float sm[];
    float* W2s  = sm + OFF_W2S;
    float* hid  = sm + OFF_HID;     // reused as ms after GEMM2
    float* wr_s = sm + OFF_WR;
    float* we_s = sm + OFF_WE;
    float* b1_s = sm + OFF_B1;
    float* at_s = sm + OFF_ATT;
    float* b2_s = sm + OFF_B2;
    float* rd_s = sm + OFF_RAD;
    float* ea_s = sm + OFF_EA;
    float* gt_s = sm + OFF_GATE;
    int* rows_s = (int*)(sm + OFF_ROWS);
    int* cols_s = (int*)(sm + OFF_COLS);

    int t = threadIdx.x;
    int e0 = blockIdx.x * TILE_E;

    if (t < TILE_E) {
        rows_s[t] = ei[e0 + t];
        rd_s[t] = radial[e0 + t];
        ea_s[t] = ea[e0 + t];
    } else if (t < 2 * TILE_E) {
        cols_s[t - TILE_E] = ei[N_EDGES + e0 + (t - TILE_E)];
    }
    for (int idx = t; idx < 5 * 128; idx += 256) {
        int a = idx >> 7, c = idx & 127;
        float v;
        if (a == 0) v = wr[c];
        else if (a == 1) v = we[c];
        else if (a == 2) v = b1[c];
        else if (a == 3) v = attw[c];
        else v = B2[c];
        sm[OFF_WR + a * 128 + c] = v;
    }
    // stage W2 (tf32-rounded), padded stride 136
    for (int idx = t; idx < 128 * 32; idx += 256) {
        int kk = idx >> 5, c4 = (idx & 31) * 4;
        float4 v = *(const float4*)(W2 + (size_t)kk * 128 + c4);
        v.x = __uint_as_float(tf32r(v.x));
        v.y = __uint_as_float(tf32r(v.y));
        v.z = __uint_as_float(tf32r(v.z));
        v.w = __uint_as_float(tf32r(v.w));
        *(float4*)&W2s[kk * 136 + c4] = v;
    }
    __syncthreads();

    // hid = silu(P[row]+Q[col]+rad*wr+ea*we+b1), tf32-rounded
    for (int idx = t; idx < TILE_E * 128; idx += 256) {
        int e = idx >> 7, c = idx & 127;
        float v = P[(size_t)rows_s[e] * 128 + c] + Q[(size_t)cols_s[e] * 128 + c]
                + rd_s[e] * wr_s[c] + ea_s[e] * we_s[c] + b1_s[c];
        hid[e * 132 + c] = __uint_as_float(tf32r(siluf(v)));
    }
    __syncthreads();

    // GEMM2 via tensor cores: warp w -> edges (w&3)*16.. , cols (w>>2)*64..
    int w = t >> 5, lane = t & 31;
    int g = lane >> 2, t4 = lane & 3;
    int eg0 = (w & 3) * 16, ng0 = (w >> 2) * 64;
    float acc[8][4];
#pragma unroll
    for (int nt = 0; nt < 8; nt++) { acc[nt][0] = acc[nt][1] = acc[nt][2] = acc[nt][3] = 0.f; }

#pragma unroll 4
    for (int k0 = 0; k0 < 128; k0 += 4) {
        int k = k0 + t4;
        uint32_t a0 = __float_as_uint(hid[(eg0 + g) * 132 + k]);
        uint32_t a1 = __float_as_uint(hid[(eg0 + g + 8) * 132 + k]);
#pragma unroll
        for (int nt = 0; nt < 8; nt++) {
            uint32_t b0 = __float_as_uint(W2s[k * 136 + ng0 + nt * 8 + g]);
            asm volatile(
                "mma.sync.aligned.m16n8k4.row.col.f32.tf32.tf32.f32 "
                "{%0,%1,%2,%3}, {%4,%5}, {%6}, {%0,%1,%2,%3};"
                : "+f"(acc[nt][0]), "+f"(acc[nt][1]), "+f"(acc[nt][2]), "+f"(acc[nt][3])
                : "r"(a0), "r"(a1), "r"(b0));
        }
    }
    __syncthreads();   // all hid reads done; reuse as ms

    // epilogue: ms = silu(acc + b2)
#pragma unroll
    for (int nt = 0; nt < 8; nt++) {
        int c0 = ng0 + nt * 8 + 2 * t4;
        int r0 = eg0 + g, r1 = r0 + 8;
        hid[r0 * 132 + c0]     = siluf(acc[nt][0] + b2_s[c0]);
        hid[r0 * 132 + c0 + 1] = siluf(acc[nt][1] + b2_s[c0 + 1]);
        hid[r1 * 132 + c0]     = siluf(acc[nt][2] + b2_s[c0]);
        hid[r1 * 132 + c0 + 1] = siluf(acc[nt][3] + b2_s[c0 + 1]);
    }
    __syncthreads();

    // gate[e] = sigmoid(m[e].attw + attb) : 4 threads per edge
    {
        int e = t >> 2, l4 = t & 3;
        float s = 0.f;
#pragma unroll
        for (int c = l4; c < 128; c += 4) s += hid[e * 132 + c] * at_s[c];
        s += __shfl_down_sync(0xffffffffu, s, 2, 4);
        s += __shfl_down_sync(0xffffffffu, s, 1, 4);
        if (l4 == 0) gt_s[e] = sigmf(s + attb[0]);
    }
    __syncthreads();

    // scatter: agg[row[e]] += m[e]*gate[e]
    for (int idx = t; idx < TILE_E * 128; idx += 256) {
        int e = idx >> 7, c = idx & 127;
        atomicAdd(agg + (size_t)rows_s[e] * 128 + c, hid[e * 132 + c] * gt_s[e]);
    }
}

// ---------------- node_in = [h, agg, h0] ----------------
__global__ void concat_node(const float* __restrict__ h, const float* __restrict__ agg,
                            const float* __restrict__ na, float* __restrict__ out) {
    int idx = blockIdx.x * blockDim.x + threadIdx.x;
    if (idx >= N_NODES * NODE_IN) return;
    int n = idx / NODE_IN, k = idx % NODE_IN;
    float v;
    if (k < 128)      v = h[(size_t)n * 128 + k];
    else if (k < 256) v = agg[(size_t)n * 128 + (k - 128)];
    else              v = na[(size_t)n * F_NODE + (k - 256)];
    out[idx] = v;
}

// ---------------- final head: out = sigmoid(X @ w + b), K=192, CO=1 ----------------
__global__ void last2_kernel(const float* __restrict__ X, const float* __restrict__ w,
                             const float* __restrict__ b, float* __restrict__ out) {
    int gt = blockIdx.x * blockDim.x + threadIdx.x;
    int n = gt >> 5, lane = gt & 31;
    if (n >= N_NODES) return;
    float s = 0.f;
    for (int c = lane; c < 192; c += 32) s += X[(size_t)n * 192 + c] * w[c];
#pragma unroll
    for (int o = 16; o; o >>= 1) s += __shfl_down_sync(0xffffffffu, s, o);
    if (lane == 0) out[n] = sigmf(s + b[0]);
}

// ---------------- launch ----------------
extern "C" void kernel_launch(void* const* d_in, const int* in_sizes, int n_in,
                              void* d_out, int out_size) {
    const float* node_attrs = (const float*)d_in[0];
    const float* coords     = (const float*)d_in[1];
    const int*   ei         = (const int*)d_in[2];
    const float* ea         = (const float*)d_in[3];
    const float* emb_w  = (const float*)d_in[4];
    const float* emb_b  = (const float*)d_in[5];
    const float* edge_w1 = (const float*)d_in[6];
    const float* edge_b1 = (const float*)d_in[7];
    const float* edge_w2 = (const float*)d_in[8];
    const float* edge_b2 = (const float*)d_in[9];
    const float* att_w   = (const float*)d_in[10];
    const float* att_b   = (const float*)d_in[11];
    const float* node_w1 = (const float*)d_in[12];
    const float* node_b1 = (const float*)d_in[13];
    const float* node_w2 = (const float*)d_in[14];
    const float* node_b2 = (const float*)d_in[15];
    const float* dec_w1  = (const float*)d_in[16];
    const float* dec_b1  = (const float*)d_in[17];
    const float* dec_w2  = (const float*)d_in[18];
    const float* dec_b2  = (const float*)d_in[19];
    const float* ffnn_w1 = (const float*)d_in[20];
    const float* ffnn_b1 = (const float*)d_in[21];
    const float* ffnn_w2 = (const float*)d_in[22];
    const float* ffnn_b2 = (const float*)d_in[23];
    const float* last_w1 = (const float*)d_in[24];
    const float* last_b1 = (const float*)d_in[25];
    const float* last_w2 = (const float*)d_in[26];
    const float* last_b2 = (const float*)d_in[27];

    float *h, *P, *Q, *agg, *tmp, *nodein, *esm1, *cat, *last, *radial;
    cudaGetSymbolAddress((void**)&h, g_h);
    cudaGetSymbolAddress((void**)&P, g_P);
    cudaGetSymbolAddress((void**)&Q, g_Q);
    cudaGetSymbolAddress((void**)&agg, g_agg);
    cudaGetSymbolAddress((void**)&tmp, g_tmp);
    cudaGetSymbolAddress((void**)&nodein, g_nodein);
    cudaGetSymbolAddress((void**)&esm1, g_esm1);
    cudaGetSymbolAddress((void**)&cat, g_cat);
    cudaGetSymbolAddress((void**)&last, g_last);
    cudaGetSymbolAddress((void**)&radial, g_radial);

    cudaFuncSetAttribute(edge_kernel, cudaFuncAttributeMaxDynamicSharedMemorySize, EDGE_SMEM);

    const int GB = (N_NODES + 31) / 32;

    radial_kernel<<<(N_EDGES + 255) / 256, 256>>>(coords, ei, radial);

    // h = h0 @ emb_w + emb_b
    gemm_act<0, false, true><<<dim3(GB, 1), 256>>>(node_attrs, F_NODE, emb_w, emb_b,
                                                   h, 128, N_NODES, F_STRUCT, 128);
    // ESM branch (independent): writes cat[:,128:192]
    gemm_act<2, false, true><<<dim3(GB, 2), 256>>>(node_attrs + F_STRUCT, F_NODE, ffnn_w1, ffnn_b1,
                                                   esm1, 256, N_NODES, F_ESM, 256);
    gemm_act<2, false, true><<<dim3(GB, 1), 256>>>(esm1, 256, ffnn_w2, ffnn_b2,
                                                   cat + 128, 192, N_NODES, 256, 64);

    for (int i = 0; i < NLAYERS; i++) {
        const float* W1 = edge_w1 + (size_t)i * EDGE_IN * 128;
        // P = h @ W1[0:128], Q = h @ W1[128:256]  (exact GEMM1 decomposition)
        gemm_act<0, false, false><<<dim3(GB, 1), 256>>>(h, 128, W1, nullptr,
                                                        P, 128, N_NODES, 128, 128);
        gemm_act<0, false, false><<<dim3(GB, 1), 256>>>(h, 128, W1 + 128 * 128, nullptr,
                                                        Q, 128, N_NODES, 128, 128);
        cudaMemsetAsync(agg, 0, (size_t)N_NODES * 128 * sizeof(float));
        edge_kernel<<<N_EDGES / TILE_E, 256, EDGE_SMEM>>>(P, Q, radial, ea, ei,
                                               W1 + 256 * 128,          // wr
                                               W1 + 257 * 128,          // we
                                               edge_b1 + (size_t)i * 128,
                                               edge_w2 + (size_t)i * 128 * 128,
                                               edge_b2 + (size_t)i * 128,
                                               att_w + (size_t)i * 128,
                                               att_b + i, agg);
        concat_node<<<(N_NODES * NODE_IN + 255) / 256, 256>>>(h, agg, node_attrs, nodein);
        gemm_act<1, false, true><<<dim3(GB, 1), 256>>>(nodein, NODE_IN,
                                                       node_w1 + (size_t)i * NODE_IN * 128,
                                                       node_b1 + (size_t)i * 128,
                                                       tmp, 128, N_NODES, NODE_IN, 128);
        gemm_act<0, true, true><<<dim3(GB, 1), 256>>>(tmp, 128,
                                                      node_w2 + (size_t)i * 128 * 128,
                                                      node_b2 + (size_t)i * 128,
                                                      h, 128, N_NODES, 128, 128);
    }

    // decoder -> cat[:,0:128]
    gemm_act<1, false, true><<<dim3(GB, 1), 256>>>(h, 128, dec_w1, dec_b1, tmp, 128, N_NODES, 128, 128);
    gemm_act<0, false, true><<<dim3(GB, 1), 256>>>(tmp, 128, dec_w2, dec_b2, cat, 192, N_NODES, 128, 128);

    // final head
    gemm_act<1, false, true><<<dim3(GB, 2), 256>>>(cat, 192, last_w1, last_b1, last, 192, N_NODES, 192, 192);
    last2_kernel<<<(N_NODES * 32 + 255) / 256, 256>>>(last, last_w2, last_b2, (float*)d_out);
}

// round 4
// speedup vs baseline: 2.7933x; 1.2746x over previous
#include <cuda_runtime.h>
#include <math.h>
#include <stdint.h>

#define N_NODES 50000
#define N_EDGES 800000
#define H1 128
#define F_NODE 1363
#define F_STRUCT 83
#define F_ESM 1280
#define EDGE_IN 258
#define NODE_IN 339
#define NODE_IN_P 340
#define NLAYERS 4

// ---------------- scratch (static device globals; no allocs) ----------------
__device__ float g_h[N_NODES * H1];
__device__ float g_P[N_NODES * H1];
__device__ float g_Q[N_NODES * H1];
__device__ float g_agg[N_NODES * H1];
__device__ float g_tmp[N_NODES * H1];
__device__ float g_nodein[N_NODES * NODE_IN_P];
__device__ float g_esmin[N_NODES * F_ESM];
__device__ float g_esm1[N_NODES * 256];
__device__ float g_cat[N_NODES * 192];
__device__ float g_last[N_NODES * 192];
__device__ float g_radial[N_EDGES];

__device__ __forceinline__ float siluf(float x) { return x / (1.f + __expf(-x)); }
__device__ __forceinline__ float sigmf(float x) { return 1.f / (1.f + __expf(-x)); }
__device__ __forceinline__ float tf32f(float x) {
    uint32_t r; asm("cvt.rna.tf32.f32 %0, %1;" : "=r"(r) : "f"(x));
    return __uint_as_float(r);
}
__device__ __forceinline__ uint32_t f2u(float x) { return __float_as_uint(x); }

#define MMA8(d, a, b0, b1)                                                    \
    asm volatile(                                                             \
        "mma.sync.aligned.m16n8k8.row.col.f32.tf32.tf32.f32 "                 \
        "{%0,%1,%2,%3}, {%4,%5,%6,%7}, {%8,%9}, {%0,%1,%2,%3};"               \
        : "+f"(d[0]), "+f"(d[1]), "+f"(d[2]), "+f"(d[3])                      \
        : "r"(a[0]), "r"(a[1]), "r"(a[2]), "r"(a[3]), "r"(b0), "r"(b1))

// ---------------- radial ----------------
__global__ void radial_kernel(const float* __restrict__ coords,
                              const int* __restrict__ ei,
                              float* __restrict__ radial) {
    int e = blockIdx.x * blockDim.x + threadIdx.x;
    if (e >= N_EDGES) return;
    int r = ei[e], c = ei[N_EDGES + e];
    float dx = coords[r * 3 + 0] - coords[c * 3 + 0];
    float dy = coords[r * 3 + 1] - coords[c * 3 + 1];
    float dz = coords[r * 3 + 2] - coords[c * 3 + 2];
    radial[e] = dx * dx + dy * dy + dz * dz;
}

// ---------------- copy ESM slice to aligned buffer ----------------
__global__ void copy_esm(const float* __restrict__ na, float* __restrict__ dst) {
    int n = blockIdx.x, t = threadIdx.x;
    const float* src = na + (size_t)n * F_NODE + F_STRUCT;
    float* d = dst + (size_t)n * F_ESM;
#pragma unroll
    for (int c = t; c < F_ESM; c += 256) d[c] = src[c];
}

// ---------------- tf32 tensor-core GEMM: Y = act(X@W [+b]) [+Y] ----------------
// 256 threads = 8 warps (4 m x 2 n). Block tile 128x128, warp tile 32x64, BK=32.
#define BKT 32
template <int ACT, bool RESID, bool BIAS, bool VECX>
__global__ __launch_bounds__(256) void gemm_tc(
        const float* __restrict__ X, int ldx,
        const float* __restrict__ W, const float* __restrict__ B,
        float* __restrict__ Y, int ldy,
        int M, int K, int CO) {
    __shared__ float As[128][36];
    __shared__ float Ws[BKT][136];
    int t = threadIdx.x;
    int warp = t >> 5, lane = t & 31;
    int g = lane >> 2, t4 = lane & 3;
    int wm = warp & 3, wn = warp >> 1 & 0; // placeholder (fixed below)
    wn = warp >> 2;                        // 0..1
    int m0 = blockIdx.x * 128, cb = blockIdx.y * 128;
    float acc[2][8][4];
#pragma unroll
    for (int i = 0; i < 2; i++)
#pragma unroll
        for (int nt = 0; nt < 8; nt++)
            acc[i][nt][0] = acc[i][nt][1] = acc[i][nt][2] = acc[i][nt][3] = 0.f;

    for (int k0 = 0; k0 < K; k0 += BKT) {
        __syncthreads();
        if (VECX) {
            for (int idx = t; idx < 128 * 8; idx += 256) {
                int r = idx >> 3, c4 = (idx & 7) * 4;
                float4 v = {0.f, 0.f, 0.f, 0.f};
                if (m0 + r < M && k0 + c4 < K)
                    v = *(const float4*)(X + (size_t)(m0 + r) * ldx + k0 + c4);
                v.x = tf32f(v.x); v.y = tf32f(v.y); v.z = tf32f(v.z); v.w = tf32f(v.w);
                *(float4*)&As[r][c4] = v;
            }
        } else {
            for (int idx = t; idx < 128 * 32; idx += 256) {
                int r = idx >> 5, c = idx & 31;
                float v = 0.f;
                if (m0 + r < M && k0 + c < K)
                    v = X[(size_t)(m0 + r) * ldx + k0 + c];
                As[r][c] = tf32f(v);
            }
        }
        for (int idx = t; idx < BKT * 32; idx += 256) {
            int kk = idx >> 5, c4 = (idx & 31) * 4;
            float4 v = {0.f, 0.f, 0.f, 0.f};
            if (k0 + kk < K && cb + c4 < CO)   // CO is a multiple of 4
                v = *(const float4*)(W + (size_t)(k0 + kk) * CO + cb + c4);
            v.x = tf32f(v.x); v.y = tf32f(v.y); v.z = tf32f(v.z); v.w = tf32f(v.w);
            *(float4*)&Ws[kk][c4] = v;
        }
        __syncthreads();
#pragma unroll
        for (int ks = 0; ks < BKT; ks += 8) {
            uint32_t a[2][4];
#pragma unroll
            for (int i = 0; i < 2; i++) {
                int r = wm * 32 + i * 16 + g;
                a[i][0] = f2u(As[r][ks + t4]);
                a[i][1] = f2u(As[r + 8][ks + t4]);
                a[i][2] = f2u(As[r][ks + t4 + 4]);
                a[i][3] = f2u(As[r + 8][ks + t4 + 4]);
            }
#pragma unroll
            for (int nt = 0; nt < 8; nt++) {
                int c = wn * 64 + nt * 8 + g;
                uint32_t b0 = f2u(Ws[ks + t4][c]);
                uint32_t b1 = f2u(Ws[ks + t4 + 4][c]);
                MMA8(acc[0][nt], a[0], b0, b1);
                MMA8(acc[1][nt], a[1], b0, b1);
            }
        }
    }

    // epilogue
#pragma unroll
    for (int i = 0; i < 2; i++) {
        int rA = m0 + wm * 32 + i * 16 + g;
        int rB = rA + 8;
#pragma unroll
        for (int nt = 0; nt < 8; nt++) {
            int c = cb + wn * 64 + nt * 8 + 2 * t4;
            if (c >= CO) continue;
            float b0v = 0.f, b1v = 0.f;
            if (BIAS) { b0v = B[c]; if (c + 1 < CO) b1v = B[c + 1]; }
            bool two = (c + 1 < CO);
#pragma unroll
            for (int h2 = 0; h2 < 2; h2++) {
                int m = h2 ? rB : rA;
                if (m >= M) continue;
                float x0 = acc[i][nt][h2 * 2 + 0] + b0v;
                float x1 = acc[i][nt][h2 * 2 + 1] + b1v;
                if (ACT == 1) { x0 = siluf(x0); x1 = siluf(x1); }
                if (ACT == 2) { x0 = fmaxf(x0, 0.f); x1 = fmaxf(x1, 0.f); }
                float* yp = Y + (size_t)m * ldy + c;
                if (two) {
                    if (RESID) { float2 o = *(const float2*)yp; x0 += o.x; x1 += o.y; }
                    float2 o; o.x = x0; o.y = x1;
                    *(float2*)yp = o;
                } else {
                    if (RESID) x0 += yp[0];
                    yp[0] = x0;
                }
            }
        }
    }
}

// ---------------- fused edge layer: tf32 m16n8k8 GEMM2 ----------------
#define TILE_E 64
#define OFF_W2S   0                    // [128][136]
#define OFF_HID   (128*136)            // [64][132]
#define OFF_WR    (OFF_HID + 64*132)
#define OFF_WE    (OFF_WR + 128)
#define OFF_B1    (OFF_WE + 128)
#define OFF_ATT   (OFF_B1 + 128)
#define OFF_B2    (OFF_ATT + 128)
#define OFF_RAD   (OFF_B2 + 128)
#define OFF_EA    (OFF_RAD + 64)
#define OFF_GATE  (OFF_EA + 64)
#define OFF_ROWS  (OFF_GATE + 64)
#define OFF_COLS  (OFF_ROWS + 64)
#define EDGE_SMEM ((OFF_COLS + 64) * 4)

__global__ __launch_bounds__(256) void edge_kernel(
        const float* __restrict__ P, const float* __restrict__ Q,
        const float* __restrict__ radial, const float* __restrict__ ea,
        const int* __restrict__ ei,
        const float* __restrict__ wr, const float* __restrict__ we,
        const float* __restrict__ b1,
        const float* __restrict__ W2, const float* __restrict__ B2,
        const float* __restrict__ attw, const float* __restrict__ attb,
        float* __restrict__ agg) {
    extern __shared__ float sm[];
    float* W2s  = sm + OFF_W2S;
    float* hid  = sm + OFF_HID;
    float* wr_s = sm + OFF_WR;
    float* we_s = sm + OFF_WE;
    float* b1_s = sm + OFF_B1;
    float* at_s = sm + OFF_ATT;
    float* b2_s = sm + OFF_B2;
    float* rd_s = sm + OFF_RAD;
    float* ea_s = sm + OFF_EA;
    float* gt_s = sm + OFF_GATE;
    int* rows_s = (int*)(sm + OFF_ROWS);
    int* cols_s = (int*)(sm + OFF_COLS);

    int t = threadIdx.x;
    int e0 = blockIdx.x * TILE_E;

    if (t < TILE_E) {
        rows_s[t] = ei[e0 + t];
        rd_s[t] = radial[e0 + t];
        ea_s[t] = ea[e0 + t];
    } else if (t < 2 * TILE_E) {
        cols_s[t - TILE_E] = ei[N_EDGES + e0 + (t - TILE_E)];
    }
    for (int idx = t; idx < 5 * 128; idx += 256) {
        int a = idx >> 7, c = idx & 127;
        float v;
        if (a == 0) v = wr[c];
        else if (a == 1) v = we[c];
        else if (a == 2) v = b1[c];
        else if (a == 3) v = attw[c];
        else v = B2[c];
        sm[OFF_WR + a * 128 + c] = v;
    }
    for (int idx = t; idx < 128 * 32; idx += 256) {
        int kk = idx >> 5, c4 = (idx & 31) * 4;
        float4 v = *(const float4*)(W2 + (size_t)kk * 128 + c4);
        v.x = tf32f(v.x); v.y = tf32f(v.y); v.z = tf32f(v.z); v.w = tf32f(v.w);
        *(float4*)&W2s[kk * 136 + c4] = v;
    }
    __syncthreads();

    for (int idx = t; idx < TILE_E * 128; idx += 256) {
        int e = idx >> 7, c = idx & 127;
        float v = P[(size_t)rows_s[e] * 128 + c] + Q[(size_t)cols_s[e] * 128 + c]
                + rd_s[e] * wr_s[c] + ea_s[e] * we_s[c] + b1_s[c];
        hid[e * 132 + c] = tf32f(siluf(v));
    }
    __syncthreads();

    int w = t >> 5, lane = t & 31;
    int g = lane >> 2, t4 = lane & 3;
    int eg0 = (w & 3) * 16, ng0 = (w >> 2) * 64;
    float acc[8][4];
#pragma unroll
    for (int nt = 0; nt < 8; nt++) { acc[nt][0] = acc[nt][1] = acc[nt][2] = acc[nt][3] = 0.f; }

#pragma unroll
    for (int k0 = 0; k0 < 128; k0 += 8) {
        uint32_t a[4];
        a[0] = f2u(hid[(eg0 + g) * 132 + k0 + t4]);
        a[1] = f2u(hid[(eg0 + g + 8) * 132 + k0 + t4]);
        a[2] = f2u(hid[(eg0 + g) * 132 + k0 + t4 + 4]);
        a[3] = f2u(hid[(eg0 + g + 8) * 132 + k0 + t4 + 4]);
#pragma unroll
        for (int nt = 0; nt < 8; nt++) {
            uint32_t b0 = f2u(W2s[(k0 + t4) * 136 + ng0 + nt * 8 + g]);
            uint32_t b1v = f2u(W2s[(k0 + t4 + 4) * 136 + ng0 + nt * 8 + g]);
            MMA8(acc[nt], a, b0, b1v);
        }
    }
    __syncthreads();   // all hid reads done; reuse as ms

#pragma unroll
    for (int nt = 0; nt < 8; nt++) {
        int c0 = ng0 + nt * 8 + 2 * t4;
        int r0 = eg0 + g, r1 = r0 + 8;
        hid[r0 * 132 + c0]     = siluf(acc[nt][0] + b2_s[c0]);
        hid[r0 * 132 + c0 + 1] = siluf(acc[nt][1] + b2_s[c0 + 1]);
        hid[r1 * 132 + c0]     = siluf(acc[nt][2] + b2_s[c0]);
        hid[r1 * 132 + c0 + 1] = siluf(acc[nt][3] + b2_s[c0 + 1]);
    }
    __syncthreads();

    {
        int e = t >> 2, l4 = t & 3;
        float s = 0.f;
#pragma unroll
        for (int c = l4; c < 128; c += 4) s += hid[e * 132 + c] * at_s[c];
        s += __shfl_down_sync(0xffffffffu, s, 2, 4);
        s += __shfl_down_sync(0xffffffffu, s, 1, 4);
        if (l4 == 0) gt_s[e] = sigmf(s + attb[0]);
    }
    __syncthreads();

    for (int idx = t; idx < TILE_E * 128; idx += 256) {
        int e = idx >> 7, c = idx & 127;
        atomicAdd(agg + (size_t)rows_s[e] * 128 + c, hid[e * 132 + c] * gt_s[e]);
    }
}

// ---------------- node_in = [h, agg, h0] (stride 340, col 339 zeroed) --------
__global__ void concat_node(const float* __restrict__ h, const float* __restrict__ agg,
                            const float* __restrict__ na, float* __restrict__ out) {
    int idx = blockIdx.x * blockDim.x + threadIdx.x;
    if (idx >= N_NODES * NODE_IN_P) return;
    int n = idx / NODE_IN_P, k = idx % NODE_IN_P;
    float v;
    if (k < 128)      v = h[(size_t)n * 128 + k];
    else if (k < 256) v = agg[(size_t)n * 128 + (k - 128)];
    else if (k < 339) v = na[(size_t)n * F_NODE + (k - 256)];
    else              v = 0.f;
    out[idx] = v;
}

// ---------------- final head ----------------
__global__ void last2_kernel(const float* __restrict__ X, const float* __restrict__ w,
                             const float* __restrict__ b, float* __restrict__ out) {
    int gt = blockIdx.x * blockDim.x + threadIdx.x;
    int n = gt >> 5, lane = gt & 31;
    if (n >= N_NODES) return;
    float s = 0.f;
    for (int c = lane; c < 192; c += 32) s += X[(size_t)n * 192 + c] * w[c];
#pragma unroll
    for (int o = 16; o; o >>= 1) s += __shfl_down_sync(0xffffffffu, s, o);
    if (lane == 0) out[n] = sigmf(s + b[0]);
}

// ---------------- launch ----------------
extern "C" void kernel_launch(void* const* d_in, const int* in_sizes, int n_in,
                              void* d_out, int out_size) {
    const float* node_attrs = (const float*)d_in[0];
    const float* coords     = (const float*)d_in[1];
    const int*   ei         = (const int*)d_in[2];
    const float* ea         = (const float*)d_in[3];
    const float* emb_w  = (const float*)d_in[4];
    const float* emb_b  = (const float*)d_in[5];
    const float* edge_w1 = (const float*)d_in[6];
    const float* edge_b1 = (const float*)d_in[7];
    const float* edge_w2 = (const float*)d_in[8];
    const float* edge_b2 = (const float*)d_in[9];
    const float* att_w   = (const float*)d_in[10];
    const float* att_b   = (const float*)d_in[11];
    const float* node_w1 = (const float*)d_in[12];
    const float* node_b1 = (const float*)d_in[13];
    const float* node_w2 = (const float*)d_in[14];
    const float* node_b2 = (const float*)d_in[15];
    const float* dec_w1  = (const float*)d_in[16];
    const float* dec_b1  = (const float*)d_in[17];
    const float* dec_w2  = (const float*)d_in[18];
    const float* dec_b2  = (const float*)d_in[19];
    const float* ffnn_w1 = (const float*)d_in[20];
    const float* ffnn_b1 = (const float*)d_in[21];
    const float* ffnn_w2 = (const float*)d_in[22];
    const float* ffnn_b2 = (const float*)d_in[23];
    const float* last_w1 = (const float*)d_in[24];
    const float* last_b1 = (const float*)d_in[25];
    const float* last_w2 = (const float*)d_in[26];
    const float* last_b2 = (const float*)d_in[27];

    float *h, *P, *Q, *agg, *tmp, *nodein, *esmin, *esm1, *cat, *last, *radial;
    cudaGetSymbolAddress((void**)&h, g_h);
    cudaGetSymbolAddress((void**)&P, g_P);
    cudaGetSymbolAddress((void**)&Q, g_Q);
    cudaGetSymbolAddress((void**)&agg, g_agg);
    cudaGetSymbolAddress((void**)&tmp, g_tmp);
    cudaGetSymbolAddress((void**)&nodein, g_nodein);
    cudaGetSymbolAddress((void**)&esmin, g_esmin);
    cudaGetSymbolAddress((void**)&esm1, g_esm1);
    cudaGetSymbolAddress((void**)&cat, g_cat);
    cudaGetSymbolAddress((void**)&last, g_last);
    cudaGetSymbolAddress((void**)&radial, g_radial);

    cudaFuncSetAttribute(edge_kernel, cudaFuncAttributeMaxDynamicSharedMemorySize, EDGE_SMEM);

    const int GBM = (N_NODES + 127) / 128;   // 391

    radial_kernel<<<(N_EDGES + 255) / 256, 256>>>(coords, ei, radial);
    copy_esm<<<N_NODES, 256>>>(node_attrs, esmin);

    // h = h0 @ emb_w + emb_b  (scalar-X path: node_attrs rows are misaligned)
    gemm_tc<0, false, true, false><<<dim3(GBM, 1), 256>>>(node_attrs, F_NODE, emb_w, emb_b,
                                                          h, 128, N_NODES, F_STRUCT, 128);
    // ESM branch -> cat[:,128:192]
    gemm_tc<2, false, true, true><<<dim3(GBM, 2), 256>>>(esmin, F_ESM, ffnn_w1, ffnn_b1,
                                                         esm1, 256, N_NODES, F_ESM, 256);
    gemm_tc<2, false, true, true><<<dim3(GBM, 1), 256>>>(esm1, 256, ffnn_w2, ffnn_b2,
                                                         cat + 128, 192, N_NODES, 256, 64);

    for (int i = 0; i < NLAYERS; i++) {
        const float* W1 = edge_w1 + (size_t)i * EDGE_IN * 128;
        gemm_tc<0, false, false, true><<<dim3(GBM, 1), 256>>>(h, 128, W1, nullptr,
                                                              P, 128, N_NODES, 128, 128);
        gemm_tc<0, false, false, true><<<dim3(GBM, 1), 256>>>(h, 128, W1 + 128 * 128, nullptr,
                                                              Q, 128, N_NODES, 128, 128);
        cudaMemsetAsync(agg, 0, (size_t)N_NODES * 128 * sizeof(float));
        edge_kernel<<<N_EDGES / TILE_E, 256, EDGE_SMEM>>>(P, Q, radial, ea, ei,
                                               W1 + 256 * 128, W1 + 257 * 128,
                                               edge_b1 + (size_t)i * 128,
                                               edge_w2 + (size_t)i * 128 * 128,
                                               edge_b2 + (size_t)i * 128,
                                               att_w + (size_t)i * 128,
                                               att_b + i, agg);
        concat_node<<<(N_NODES * NODE_IN_P + 255) / 256, 256>>>(h, agg, node_attrs, nodein);
        gemm_tc<1, false, true, true><<<dim3(GBM, 1), 256>>>(nodein, NODE_IN_P,
                                                             node_w1 + (size_t)i * NODE_IN * 128,
                                                             node_b1 + (size_t)i * 128,
                                                             tmp, 128, N_NODES, NODE_IN, 128);
        gemm_tc<0, true, true, true><<<dim3(GBM, 1), 256>>>(tmp, 128,
                                                            node_w2 + (size_t)i * 128 * 128,
                                                            node_b2 + (size_t)i * 128,
                                                            h, 128, N_NODES, 128, 128);
    }

    // decoder -> cat[:,0:128]
    gemm_tc<1, false, true, true><<<dim3(GBM, 1), 256>>>(h, 128, dec_w1, dec_b1,
                                                         tmp, 128, N_NODES, 128, 128);
    gemm_tc<0, false, true, true><<<dim3(GBM, 1), 256>>>(tmp, 128, dec_w2, dec_b2,
                                                         cat, 192, N_NODES, 128, 128);

    // final head
    gemm_tc<1, false, true, true><<<dim3(GBM, 2), 256>>>(cat, 192, last_w1, last_b1,
                                                         last, 192, N_NODES, 192, 192);
    last2_kernel<<<(N_NODES * 32 + 255) / 256, 256>>>(last, last_w2, last_b2, (float*)d_out);
}

// round 5
// speedup vs baseline: 4.3879x; 1.5709x over previous
#include <cuda_runtime.h>
#include <math.h>
#include <stdint.h>

#define N_NODES 50000
#define N_EDGES 800000
#define H1 128
#define F_NODE 1363
#define F_STRUCT 83
#define F_ESM 1280
#define NODE_IN 339
#define NODE_IN_P 352
#define H0P 96
#define NLAYERS 4

// ---------------- scratch ----------------
__device__ float g_h[N_NODES * H1];
__device__ float g_P[N_NODES * H1];
__device__ float g_Q[N_NODES * H1];
__device__ float g_agg[N_NODES * H1];
__device__ float g_tmp[N_NODES * H1];
__device__ float g_nodein[N_NODES * NODE_IN_P];
__device__ float g_esmin[N_NODES * F_ESM];
__device__ float g_h0p[N_NODES * H0P];
__device__ float g_esm1[N_NODES * 256];
__device__ float g_cat[N_NODES * 192];
__device__ float g_last[N_NODES * 192];
__device__ float g_radial[N_EDGES];

__device__ __forceinline__ float siluf(float x) { return x / (1.f + __expf(-x)); }
__device__ __forceinline__ float sigmf(float x) { return 1.f / (1.f + __expf(-x)); }
__device__ __forceinline__ uint32_t f2u(float x) { return __float_as_uint(x); }

#define MMA8(d, a, b0, b1)                                                    \
    asm volatile(                                                             \
        "mma.sync.aligned.m16n8k8.row.col.f32.tf32.tf32.f32 "                 \
        "{%0,%1,%2,%3}, {%4,%5,%6,%7}, {%8,%9}, {%0,%1,%2,%3};"               \
        : "+f"(d[0]), "+f"(d[1]), "+f"(d[2]), "+f"(d[3])                      \
        : "r"(a[0]), "r"(a[1]), "r"(a[2]), "r"(a[3]), "r"(b0), "r"(b1))

__device__ __forceinline__ void cp_async16(uint32_t dst, const void* src, int sz) {
    asm volatile("cp.async.cg.shared.global [%0], [%1], 16, %2;"
                 :: "r"(dst), "l"(src), "r"(sz));
}
#define CP_COMMIT() asm volatile("cp.async.commit_group;")
template <int NW>
__device__ __forceinline__ void cp_wait() {
    asm volatile("cp.async.wait_group %0;" :: "n"(NW));
}

// ---------------- radial ----------------
__global__ void radial_kernel(const float* __restrict__ coords,
                              const int* __restrict__ ei,
                              float* __restrict__ radial) {
    int e = blockIdx.x * blockDim.x + threadIdx.x;
    if (e >= N_EDGES) return;
    int r = ei[e], c = ei[N_EDGES + e];
    float dx = coords[r * 3 + 0] - coords[c * 3 + 0];
    float dy = coords[r * 3 + 1] - coords[c * 3 + 1];
    float dz = coords[r * 3 + 2] - coords[c * 3 + 2];
    radial[e] = dx * dx + dy * dy + dz * dz;
}

// ---------------- copy inputs to aligned/padded buffers ----------------
__global__ void copy_inputs(const float* __restrict__ na,
                            float* __restrict__ esmd, float* __restrict__ h0p) {
    int n = blockIdx.x, t = threadIdx.x;
    const float* src = na + (size_t)n * F_NODE;
#pragma unroll
    for (int c = t; c < F_ESM; c += 256) esmd[(size_t)n * F_ESM + c] = src[F_STRUCT + c];
    if (t < H0P) h0p[(size_t)n * H0P + t] = (t < F_STRUCT) ? src[t] : 0.f;
}

// ---------------- async double-buffered tf32 GEMM ----------------
// 256 thr = 8 warps (4m x 2n); block 128x128, warp 32x64, BK=32.
// K must be a multiple of 32 (X padded); KW = real K for W predicate.
#define BKT 32
#define AS_STRIDE 36
#define WS_STRIDE 136
#define AS_SZ (128 * AS_STRIDE)
#define WS_SZ (BKT * WS_STRIDE)
#define GEMM_SMEM ((AS_SZ + WS_SZ) * 2 * 4)

template <int ACT, bool RESID, bool BIAS>
__global__ __launch_bounds__(256) void gemm_tc(
        const float* __restrict__ X, int ldx,
        const float* __restrict__ W, const float* __restrict__ B,
        float* __restrict__ Y, int ldy,
        int M, int K, int KW, int CO) {
    extern __shared__ float smn[];
    float* Asm = smn;                 // [2][128][36]
    float* Wsm = smn + 2 * AS_SZ;     // [2][32][136]
    uint32_t as_u = (uint32_t)__cvta_generic_to_shared(Asm);
    uint32_t ws_u = (uint32_t)__cvta_generic_to_shared(Wsm);

    int t = threadIdx.x;
    int warp = t >> 5, lane = t & 31;
    int g = lane >> 2, t4 = lane & 3;
    int wm = warp & 3, wn = warp >> 2;
    int m0 = blockIdx.x * 128, cb = blockIdx.y * 128;

    float acc[2][8][4];
#pragma unroll
    for (int i = 0; i < 2; i++)
#pragma unroll
        for (int nt = 0; nt < 8; nt++)
            acc[i][nt][0] = acc[i][nt][1] = acc[i][nt][2] = acc[i][nt][3] = 0.f;

    auto loadA = [&](int buf, int k0) {
#pragma unroll
        for (int i = 0; i < 4; i++) {
            int idx = t + i * 256;
            int r = idx >> 3, c4 = (idx & 7) * 4;
            uint32_t dst = as_u + (buf * AS_SZ + r * AS_STRIDE + c4) * 4;
            const float* src = X + (size_t)(m0 + r) * ldx + k0 + c4;
            cp_async16(dst, src, (m0 + r < M) ? 16 : 0);
        }
    };
    auto loadW = [&](int buf, int k0) {
#pragma unroll
        for (int i = 0; i < 4; i++) {
            int idx = t + i * 256;
            int kk = idx >> 5, c4 = (idx & 31) * 4;
            uint32_t dst = ws_u + (buf * WS_SZ + kk * WS_STRIDE + c4) * 4;
            const float* src = W + (size_t)(k0 + kk) * CO + cb + c4;
            cp_async16(dst, src, (k0 + kk < KW && cb + c4 < CO) ? 16 : 0);
        }
    };

    loadA(0, 0); loadW(0, 0); CP_COMMIT();
    int nk = K / BKT;
    int buf = 0;
    for (int ki = 0; ki < nk; ki++, buf ^= 1) {
        if (ki + 1 < nk) {
            loadA(buf ^ 1, (ki + 1) * BKT);
            loadW(buf ^ 1, (ki + 1) * BKT);
            CP_COMMIT();
            cp_wait<1>();
        } else {
            cp_wait<0>();
        }
        __syncthreads();
        const float* A = Asm + buf * AS_SZ;
        const float* Wb = Wsm + buf * WS_SZ;
#pragma unroll
        for (int ks = 0; ks < BKT; ks += 8) {
            uint32_t a[2][4];
#pragma unroll
            for (int i = 0; i < 2; i++) {
                int r = wm * 32 + i * 16 + g;
                a[i][0] = f2u(A[r * AS_STRIDE + ks + t4]);
                a[i][1] = f2u(A[(r + 8) * AS_STRIDE + ks + t4]);
                a[i][2] = f2u(A[r * AS_STRIDE + ks + t4 + 4]);
                a[i][3] = f2u(A[(r + 8) * AS_STRIDE + ks + t4 + 4]);
            }
#pragma unroll
            for (int nt = 0; nt < 8; nt++) {
                int c = wn * 64 + nt * 8 + g;
                uint32_t b0 = f2u(Wb[(ks + t4) * WS_STRIDE + c]);
                uint32_t b1 = f2u(Wb[(ks + t4 + 4) * WS_STRIDE + c]);
                MMA8(acc[0][nt], a[0], b0, b1);
                MMA8(acc[1][nt], a[1], b0, b1);
            }
        }
        __syncthreads();
    }

    // epilogue
#pragma unroll
    for (int i = 0; i < 2; i++) {
        int rA = m0 + wm * 32 + i * 16 + g;
        int rB = rA + 8;
#pragma unroll
        for (int nt = 0; nt < 8; nt++) {
            int c = cb + wn * 64 + nt * 8 + 2 * t4;
            if (c >= CO) continue;
            float b0v = 0.f, b1v = 0.f;
            if (BIAS) { b0v = B[c]; b1v = B[c + 1]; }
#pragma unroll
            for (int h2 = 0; h2 < 2; h2++) {
                int m = h2 ? rB : rA;
                if (m >= M) continue;
                float x0 = acc[i][nt][h2 * 2 + 0] + b0v;
                float x1 = acc[i][nt][h2 * 2 + 1] + b1v;
                if (ACT == 1) { x0 = siluf(x0); x1 = siluf(x1); }
                if (ACT == 2) { x0 = fmaxf(x0, 0.f); x1 = fmaxf(x1, 0.f); }
                float* yp = Y + (size_t)m * ldy + c;
                if (RESID) { float2 o = *(const float2*)yp; x0 += o.x; x1 += o.y; }
                float2 o; o.x = x0; o.y = x1;
                *(float2*)yp = o;
            }
        }
    }
}

// ---------------- fused edge layer ----------------
#define TILE_E 64
#define OFF_W2S   0                    // [128][136]
#define OFF_HID   (128*136)            // [64][132]
#define OFF_WR    (OFF_HID + 64*132)
#define OFF_WE    (OFF_WR + 128)
#define OFF_B1    (OFF_WE + 128)
#define OFF_ATT   (OFF_B1 + 128)
#define OFF_B2    (OFF_ATT + 128)
#define OFF_RAD   (OFF_B2 + 128)
#define OFF_EA    (OFF_RAD + 64)
#define OFF_GATE  (OFF_EA + 64)
#define OFF_ROWS  (OFF_GATE + 64)
#define OFF_COLS  (OFF_ROWS + 64)
#define EDGE_SMEM ((OFF_COLS + 64) * 4)

__global__ __launch_bounds__(256) void edge_kernel(
        const float* __restrict__ P, const float* __restrict__ Q,
        const float* __restrict__ radial, const float* __restrict__ ea,
        const int* __restrict__ ei,
        const float* __restrict__ wr, const float* __restrict__ we,
        const float* __restrict__ b1,
        const float* __restrict__ W2, const float* __restrict__ B2,
        const float* __restrict__ attw, const float* __restrict__ attb,
        float* __restrict__ agg) {
    extern __shared__ float sm[];
    float* W2s  = sm + OFF_W2S;
    float* hid  = sm + OFF_HID;
    float* wr_s = sm + OFF_WR;
    float* we_s = sm + OFF_WE;
    float* b1_s = sm + OFF_B1;
    float* at_s = sm + OFF_ATT;
    float* b2_s = sm + OFF_B2;
    float* rd_s = sm + OFF_RAD;
    float* ea_s = sm + OFF_EA;
    float* gt_s = sm + OFF_GATE;
    int* rows_s = (int*)(sm + OFF_ROWS);
    int* cols_s = (int*)(sm + OFF_COLS);

    int t = threadIdx.x;
    int e0 = blockIdx.x * TILE_E;

    if (t < TILE_E) {
        rows_s[t] = ei[e0 + t];
        rd_s[t] = radial[e0 + t];
        ea_s[t] = ea[e0 + t];
    } else if (t < 2 * TILE_E) {
        cols_s[t - TILE_E] = ei[N_EDGES + e0 + (t - TILE_E)];
    }
    for (int idx = t; idx < 5 * 128; idx += 256) {
        int a = idx >> 7, c = idx & 127;
        float v;
        if (a == 0) v = wr[c];
        else if (a == 1) v = we[c];
        else if (a == 2) v = b1[c];
        else if (a == 3) v = attw[c];
        else v = B2[c];
        sm[OFF_WR + a * 128 + c] = v;
    }
    for (int idx = t; idx < 128 * 32; idx += 256) {
        int kk = idx >> 5, c4 = (idx & 31) * 4;
        *(float4*)&W2s[kk * 136 + c4] = *(const float4*)(W2 + (size_t)kk * 128 + c4);
    }
    __syncthreads();

    // hid = silu(P[row]+Q[col]+rad*wr+ea*we+b1), float4 gather
#pragma unroll
    for (int i = 0; i < 8; i++) {
        int idx = t + i * 256;
        int e = idx >> 5, c4 = (idx & 31) * 4;
        float4 p = *(const float4*)(P + (size_t)rows_s[e] * 128 + c4);
        float4 q = *(const float4*)(Q + (size_t)cols_s[e] * 128 + c4);
        float rd = rd_s[e], eav = ea_s[e];
        float4 o;
        o.x = siluf(p.x + q.x + rd * wr_s[c4 + 0] + eav * we_s[c4 + 0] + b1_s[c4 + 0]);
        o.y = siluf(p.y + q.y + rd * wr_s[c4 + 1] + eav * we_s[c4 + 1] + b1_s[c4 + 1]);
        o.z = siluf(p.z + q.z + rd * wr_s[c4 + 2] + eav * we_s[c4 + 2] + b1_s[c4 + 2]);
        o.w = siluf(p.w + q.w + rd * wr_s[c4 + 3] + eav * we_s[c4 + 3] + b1_s[c4 + 3]);
        *(float4*)&hid[e * 132 + c4] = o;
    }
    __syncthreads();

    int w = t >> 5, lane = t & 31;
    int g = lane >> 2, t4 = lane & 3;
    int eg0 = (w & 3) * 16, ng0 = (w >> 2) * 64;
    float acc[8][4];
#pragma unroll
    for (int nt = 0; nt < 8; nt++) { acc[nt][0] = acc[nt][1] = acc[nt][2] = acc[nt][3] = 0.f; }

#pragma unroll
    for (int k0 = 0; k0 < 128; k0 += 8) {
        uint32_t a[4];
        a[0] = f2u(hid[(eg0 + g) * 132 + k0 + t4]);
        a[1] = f2u(hid[(eg0 + g + 8) * 132 + k0 + t4]);
        a[2] = f2u(hid[(eg0 + g) * 132 + k0 + t4 + 4]);
        a[3] = f2u(hid[(eg0 + g + 8) * 132 + k0 + t4 + 4]);
#pragma unroll
        for (int nt = 0; nt < 8; nt++) {
            uint32_t b0 = f2u(W2s[(k0 + t4) * 136 + ng0 + nt * 8 + g]);
            uint32_t b1v = f2u(W2s[(k0 + t4 + 4) * 136 + ng0 + nt * 8 + g]);
            MMA8(acc[nt], a, b0, b1v);
        }
    }
    __syncthreads();   // all hid reads done; reuse as ms

#pragma unroll
    for (int nt = 0; nt < 8; nt++) {
        int c0 = ng0 + nt * 8 + 2 * t4;
        int r0 = eg0 + g, r1 = r0 + 8;
        hid[r0 * 132 + c0]     = siluf(acc[nt][0] + b2_s[c0]);
        hid[r0 * 132 + c0 + 1] = siluf(acc[nt][1] + b2_s[c0 + 1]);
        hid[r1 * 132 + c0]     = siluf(acc[nt][2] + b2_s[c0]);
        hid[r1 * 132 + c0 + 1] = siluf(acc[nt][3] + b2_s[c0 + 1]);
    }
    __syncthreads();

    {
        int e = t >> 2, l4 = t & 3;
        float s = 0.f;
#pragma unroll
        for (int c = l4; c < 128; c += 4) s += hid[e * 132 + c] * at_s[c];
        s += __shfl_down_sync(0xffffffffu, s, 2, 4);
        s += __shfl_down_sync(0xffffffffu, s, 1, 4);
        if (l4 == 0) gt_s[e] = sigmf(s + attb[0]);
    }
    __syncthreads();

    // scatter with vector reduction: agg[row[e]] += m[e]*gate[e]
#pragma unroll
    for (int i = 0; i < 8; i++) {
        int idx = t + i * 256;
        int e = idx >> 5, c4 = (idx & 31) * 4;
        float gt = gt_s[e];
        float4 m4 = *(const float4*)&hid[e * 132 + c4];
        float* ptr = agg + (size_t)rows_s[e] * 128 + c4;
        asm volatile("red.global.add.v4.f32 [%0], {%1,%2,%3,%4};"
                     :: "l"(ptr), "f"(m4.x * gt), "f"(m4.y * gt),
                        "f"(m4.z * gt), "f"(m4.w * gt) : "memory");
    }
}

// ---------------- node_in = [h, agg, h0] (stride 352, cols 339.. zeroed) -----
__global__ void concat_node(const float* __restrict__ h, const float* __restrict__ agg,
                            const float* __restrict__ na, float* __restrict__ out) {
    int idx = blockIdx.x * blockDim.x + threadIdx.x;
    if (idx >= N_NODES * NODE_IN_P) return;
    int n = idx / NODE_IN_P, k = idx % NODE_IN_P;
    float v;
    if (k < 128)      v = h[(size_t)n * 128 + k];
    else if (k < 256) v = agg[(size_t)n * 128 + (k - 128)];
    else if (k < 339) v = na[(size_t)n * F_NODE + (k - 256)];
    else              v = 0.f;
    out[idx] = v;
}

// ---------------- final head ----------------
__global__ void last2_kernel(const float* __restrict__ X, const float* __restrict__ w,
                             const float* __restrict__ b, float* __restrict__ out) {
    int gt = blockIdx.x * blockDim.x + threadIdx.x;
    int n = gt >> 5, lane = gt & 31;
    if (n >= N_NODES) return;
    float s = 0.f;
    for (int c = lane; c < 192; c += 32) s += X[(size_t)n * 192 + c] * w[c];
#pragma unroll
    for (int o = 16; o; o >>= 1) s += __shfl_down_sync(0xffffffffu, s, o);
    if (lane == 0) out[n] = sigmf(s + b[0]);
}

// ---------------- launch ----------------
extern "C" void kernel_launch(void* const* d_in, const int* in_sizes, int n_in,
                              void* d_out, int out_size) {
    const float* node_attrs = (const float*)d_in[0];
    const float* coords     = (const float*)d_in[1];
    const int*   ei         = (const int*)d_in[2];
    const float* ea         = (const float*)d_in[3];
    const float* emb_w  = (const float*)d_in[4];
    const float* emb_b  = (const float*)d_in[5];
    const float* edge_w1 = (const float*)d_in[6];
    const float* edge_b1 = (const float*)d_in[7];
    const float* edge_w2 = (const float*)d_in[8];
    const float* edge_b2 = (const float*)d_in[9];
    const float* att_w   = (const float*)d_in[10];
    const float* att_b   = (const float*)d_in[11];
    const float* node_w1 = (const float*)d_in[12];
    const float* node_b1 = (const float*)d_in[13];
    const float* node_w2 = (const float*)d_in[14];
    const float* node_b2 = (const float*)d_in[15];
    const float* dec_w1  = (const float*)d_in[16];
    const float* dec_b1  = (const float*)d_in[17];
    const float* dec_w2  = (const float*)d_in[18];
    const float* dec_b2  = (const float*)d_in[19];
    const float* ffnn_w1 = (const float*)d_in[20];
    const float* ffnn_b1 = (const float*)d_in[21];
    const float* ffnn_w2 = (const float*)d_in[22];
    const float* ffnn_b2 = (const float*)d_in[23];
    const float* last_w1 = (const float*)d_in[24];
    const float* last_b1 = (const float*)d_in[25];
    const float* last_w2 = (const float*)d_in[26];
    const float* last_b2 = (const float*)d_in[27];

    float *h, *P, *Q, *agg, *tmp, *nodein, *esmin, *h0p, *esm1, *cat, *last, *radial;
    cudaGetSymbolAddress((void**)&h, g_h);
    cudaGetSymbolAddress((void**)&P, g_P);
    cudaGetSymbolAddress((void**)&Q, g_Q);
    cudaGetSymbolAddress((void**)&agg, g_agg);
    cudaGetSymbolAddress((void**)&tmp, g_tmp);
    cudaGetSymbolAddress((void**)&nodein, g_nodein);
    cudaGetSymbolAddress((void**)&esmin, g_esmin);
    cudaGetSymbolAddress((void**)&h0p, g_h0p);
    cudaGetSymbolAddress((void**)&esm1, g_esm1);
    cudaGetSymbolAddress((void**)&cat, g_cat);
    cudaGetSymbolAddress((void**)&last, g_last);
    cudaGetSymbolAddress((void**)&radial, g_radial);

    cudaFuncSetAttribute(edge_kernel, cudaFuncAttributeMaxDynamicSharedMemorySize, EDGE_SMEM);
    cudaFuncSetAttribute(gemm_tc<0, false, true>,  cudaFuncAttributeMaxDynamicSharedMemorySize, GEMM_SMEM);
    cudaFuncSetAttribute(gemm_tc<0, false, false>, cudaFuncAttributeMaxDynamicSharedMemorySize, GEMM_SMEM);
    cudaFuncSetAttribute(gemm_tc<0, true, true>,   cudaFuncAttributeMaxDynamicSharedMemorySize, GEMM_SMEM);
    cudaFuncSetAttribute(gemm_tc<1, false, true>,  cudaFuncAttributeMaxDynamicSharedMemorySize, GEMM_SMEM);
    cudaFuncSetAttribute(gemm_tc<2, false, true>,  cudaFuncAttributeMaxDynamicSharedMemorySize, GEMM_SMEM);

    const int GBM = (N_NODES + 127) / 128;   // 391

    radial_kernel<<<(N_EDGES + 255) / 256, 256>>>(coords, ei, radial);
    copy_inputs<<<N_NODES, 256>>>(node_attrs, esmin, h0p);

    // h = h0 @ emb_w + emb_b   (K=96 padded, KW=83)
    gemm_tc<0, false, true><<<dim3(GBM, 1), 256, GEMM_SMEM>>>(
        h0p, H0P, emb_w, emb_b, h, 128, N_NODES, H0P, F_STRUCT, 128);
    // ESM branch -> cat[:,128:192]
    gemm_tc<2, false, true><<<dim3(GBM, 2), 256, GEMM_SMEM>>>(
        esmin, F_ESM, ffnn_w1, ffnn_b1, esm1, 256, N_NODES, F_ESM, F_ESM, 256);
    gemm_tc<2, false, true><<<dim3(GBM, 1), 256, GEMM_SMEM>>>(
        esm1, 256, ffnn_w2, ffnn_b2, cat + 128, 192, N_NODES, 256, 256, 64);

    for (int i = 0; i < NLAYERS; i++) {
        const float* W1 = edge_w1 + (size_t)i * 258 * 128;
        gemm_tc<0, false, false><<<dim3(GBM, 1), 256, GEMM_SMEM>>>(
            h, 128, W1, nullptr, P, 128, N_NODES, 128, 128, 128);
        gemm_tc<0, false, false><<<dim3(GBM, 1), 256, GEMM_SMEM>>>(
            h, 128, W1 + 128 * 128, nullptr, Q, 128, N_NODES, 128, 128, 128);
        cudaMemsetAsync(agg, 0, (size_t)N_NODES * 128 * sizeof(float));
        edge_kernel<<<N_EDGES / TILE_E, 256, EDGE_SMEM>>>(P, Q, radial, ea, ei,
                                               W1 + 256 * 128, W1 + 257 * 128,
                                               edge_b1 + (size_t)i * 128,
                                               edge_w2 + (size_t)i * 128 * 128,
                                               edge_b2 + (size_t)i * 128,
                                               att_w + (size_t)i * 128,
                                               att_b + i, agg);
        concat_node<<<(N_NODES * NODE_IN_P + 255) / 256, 256>>>(h, agg, node_attrs, nodein);
        gemm_tc<1, false, true><<<dim3(GBM, 1), 256, GEMM_SMEM>>>(
            nodein, NODE_IN_P, node_w1 + (size_t)i * NODE_IN * 128,
            node_b1 + (size_t)i * 128, tmp, 128, N_NODES, NODE_IN_P, NODE_IN, 128);
        gemm_tc<0, true, true><<<dim3(GBM, 1), 256, GEMM_SMEM>>>(
            tmp, 128, node_w2 + (size_t)i * 128 * 128,
            node_b2 + (size_t)i * 128, h, 128, N_NODES, 128, 128, 128);
    }

    // decoder -> cat[:,0:128]
    gemm_tc<1, false, true><<<dim3(GBM, 1), 256, GEMM_SMEM>>>(
        h, 128, dec_w1, dec_b1, tmp, 128, N_NODES, 128, 128, 128);
    gemm_tc<0, false, true><<<dim3(GBM, 1), 256, GEMM_SMEM>>>(
        tmp, 128, dec_w2, dec_b2, cat, 192, N_NODES, 128, 128, 128);

    // final head
    gemm_tc<1, false, true><<<dim3(GBM, 2), 256, GEMM_SMEM>>>(
        cat, 192, last_w1, last_b1, last, 192, N_NODES, 192, 192, 192);
    last2_kernel<<<(N_NODES * 32 + 255) / 256, 256>>>(last, last_w2, last_b2, (float*)d_out);
}

// round 7
// speedup vs baseline: 4.9908x; 1.1374x over previous
#include <cuda_runtime.h>
#include <math.h>
#include <stdint.h>

#define N_NODES 50000
#define N_EDGES 800000
#define H1 128
#define F_NODE 1363
#define F_STRUCT 83
#define F_ESM 1280
#define NODE_IN 339
#define H0P 96
#define NLAYERS 4

// ---------------- scratch ----------------
__device__ float g_h[N_NODES * H1];
__device__ float g_P[N_NODES * H1];
__device__ float g_Q[N_NODES * H1];
__device__ float g_agg[N_NODES * H1];
__device__ float g_tmp[N_NODES * H1];
__device__ float g_C[N_NODES * H1];
__device__ float g_esmin[N_NODES * F_ESM];
__device__ float g_h0p[N_NODES * H0P];
__device__ float g_esm1[N_NODES * 256];
__device__ float g_cat[N_NODES * 192];
__device__ float g_last[N_NODES * 192];
__device__ float g_radial[N_EDGES];

__device__ __forceinline__ float siluf(float x) { return x / (1.f + __expf(-x)); }
__device__ __forceinline__ float sigmf(float x) { return 1.f / (1.f + __expf(-x)); }
__device__ __forceinline__ uint32_t f2u(float x) { return __float_as_uint(x); }

#define MMA8(d, a, b0, b1)                                                    \
    asm volatile(                                                             \
        "mma.sync.aligned.m16n8k8.row.col.f32.tf32.tf32.f32 "                 \
        "{%0,%1,%2,%3}, {%4,%5,%6,%7}, {%8,%9}, {%0,%1,%2,%3};"               \
        : "+f"(d[0]), "+f"(d[1]), "+f"(d[2]), "+f"(d[3])                      \
        : "r"(a[0]), "r"(a[1]), "r"(a[2]), "r"(a[3]), "r"(b0), "r"(b1))

__device__ __forceinline__ void cp_async16(uint32_t dst, const void* src, int sz) {
    asm volatile("cp.async.cg.shared.global [%0], [%1], 16, %2;"
                 :: "r"(dst), "l"(src), "r"(sz));
}
#define CP_COMMIT() asm volatile("cp.async.commit_group;")
template <int NW>
__device__ __forceinline__ void cp_wait() {
    asm volatile("cp.async.wait_group %0;" :: "n"(NW));
}

// ---------------- radial ----------------
__global__ void radial_kernel(const float* __restrict__ coords,
                              const int* __restrict__ ei,
                              float* __restrict__ radial) {
    int e = blockIdx.x * blockDim.x + threadIdx.x;
    if (e >= N_EDGES) return;
    int r = ei[e], c = ei[N_EDGES + e];
    float dx = coords[r * 3 + 0] - coords[c * 3 + 0];
    float dy = coords[r * 3 + 1] - coords[c * 3 + 1];
    float dz = coords[r * 3 + 2] - coords[c * 3 + 2];
    radial[e] = dx * dx + dy * dy + dz * dz;
}

// ---------------- copy inputs to aligned/padded buffers ----------------
__global__ void copy_inputs(const float* __restrict__ na,
                            float* __restrict__ esmd, float* __restrict__ h0p) {
    int n = blockIdx.x, t = threadIdx.x;
    const float* src = na + (size_t)n * F_NODE;
#pragma unroll
    for (int c = t; c < F_ESM; c += 256) esmd[(size_t)n * F_ESM + c] = src[F_STRUCT + c];
    if (t < H0P) h0p[(size_t)n * H0P + t] = (t < F_STRUCT) ? src[t] : 0.f;
}

// ---------------- async 3-stage tf32 GEMM ----------------
// 256 thr = 8 warps (4m x 2n); block 128x128, warp 32x64, BK=32.
// DUALX: X covers k<128, X2 covers k>=128 (both ld = ldx).
// ADDC: epilogue adds Cb[m*128 + c] before activation.
#define BKT 32
#define STAGES 3
#define AS_STRIDE 36
#define WS_STRIDE 136
#define AS_SZ (128 * AS_STRIDE)
#define WS_SZ (BKT * WS_STRIDE)
#define GEMM_SMEM ((AS_SZ + WS_SZ) * STAGES * 4)

template <int ACT, bool RESID, bool BIAS, bool DUALX, bool ADDC>
__global__ __launch_bounds__(256) void gemm_tc(
        const float* __restrict__ X, const float* __restrict__ X2, int ldx,
        const float* __restrict__ W, const float* __restrict__ B,
        const float* __restrict__ Cb,
        float* __restrict__ Y, int ldy,
        int M, int K, int KW, int CO) {
    extern __shared__ float smn[];
    float* Asm = smn;                        // [STAGES][128][36]
    float* Wsm = smn + STAGES * AS_SZ;       // [STAGES][32][136]
    uint32_t as_u = (uint32_t)__cvta_generic_to_shared(Asm);
    uint32_t ws_u = (uint32_t)__cvta_generic_to_shared(Wsm);

    int t = threadIdx.x;
    int warp = t >> 5, lane = t & 31;
    int g = lane >> 2, t4 = lane & 3;
    int wm = warp & 3, wn = warp >> 2;
    int m0 = blockIdx.x * 128, cb = blockIdx.y * 128;

    float acc[2][8][4];
#pragma unroll
    for (int i = 0; i < 2; i++)
#pragma unroll
        for (int nt = 0; nt < 8; nt++)
            acc[i][nt][0] = acc[i][nt][1] = acc[i][nt][2] = acc[i][nt][3] = 0.f;

    auto loadA = [&](int buf, int k0) {
        const float* Xs = X;
        int kb = k0;
        if (DUALX && k0 >= 128) { Xs = X2; kb = k0 - 128; }
#pragma unroll
        for (int i = 0; i < 4; i++) {
            int idx = t + i * 256;
            int r = idx >> 3, c4 = (idx & 7) * 4;
            uint32_t dst = as_u + (buf * AS_SZ + r * AS_STRIDE + c4) * 4;
            const float* src = Xs + (size_t)(m0 + r) * ldx + kb + c4;
            cp_async16(dst, src, (m0 + r < M) ? 16 : 0);
        }
    };
    auto loadW = [&](int buf, int k0) {
#pragma unroll
        for (int i = 0; i < 4; i++) {
            int idx = t + i * 256;
            int kk = idx >> 5, c4 = (idx & 31) * 4;
            uint32_t dst = ws_u + (buf * WS_SZ + kk * WS_STRIDE + c4) * 4;
            const float* src = W + (size_t)(k0 + kk) * CO + cb + c4;
            cp_async16(dst, src, (k0 + kk < KW && cb + c4 < CO) ? 16 : 0);
        }
    };

    int nk = K / BKT;
    loadA(0, 0); loadW(0, 0); CP_COMMIT();
    if (nk > 1) { loadA(1, BKT); loadW(1, BKT); }
    CP_COMMIT();

    for (int ki = 0; ki < nk; ki++) {
        int buf = ki % STAGES;
        cp_wait<1>();          // all but most-recent group complete -> group ki done
        __syncthreads();
        const float* A = Asm + buf * AS_SZ;
        const float* Wb = Wsm + buf * WS_SZ;
#pragma unroll
        for (int ks = 0; ks < BKT; ks += 8) {
            uint32_t a[2][4];
#pragma unroll
            for (int i = 0; i < 2; i++) {
                int r = wm * 32 + i * 16 + g;
                a[i][0] = f2u(A[r * AS_STRIDE + ks + t4]);
                a[i][1] = f2u(A[(r + 8) * AS_STRIDE + ks + t4]);
                a[i][2] = f2u(A[r * AS_STRIDE + ks + t4 + 4]);
                a[i][3] = f2u(A[(r + 8) * AS_STRIDE + ks + t4 + 4]);
            }
#pragma unroll
            for (int nt = 0; nt < 8; nt++) {
                int c = wn * 64 + nt * 8 + g;
                uint32_t b0 = f2u(Wb[(ks + t4) * WS_STRIDE + c]);
                uint32_t b1 = f2u(Wb[(ks + t4 + 4) * WS_STRIDE + c]);
                MMA8(acc[0][nt], a[0], b0, b1);
                MMA8(acc[1][nt], a[1], b0, b1);
            }
        }
        __syncthreads();
        if (ki + 2 < nk) {
            int nbuf = (ki + 2) % STAGES;    // FIX: prefetch into the buffer the
            loadA(nbuf, (ki + 2) * BKT);     // consumer of step ki+2 will read
            loadW(nbuf, (ki + 2) * BKT);
        }
        CP_COMMIT();
    }

    // epilogue
#pragma unroll
    for (int i = 0; i < 2; i++) {
        int rA = m0 + wm * 32 + i * 16 + g;
        int rB = rA + 8;
#pragma unroll
        for (int nt = 0; nt < 8; nt++) {
            int c = cb + wn * 64 + nt * 8 + 2 * t4;
            if (c >= CO) continue;
            float b0v = 0.f, b1v = 0.f;
            if (BIAS) { b0v = B[c]; b1v = B[c + 1]; }
#pragma unroll
            for (int h2 = 0; h2 < 2; h2++) {
                int m = h2 ? rB : rA;
                if (m >= M) continue;
                float x0 = acc[i][nt][h2 * 2 + 0] + b0v;
                float x1 = acc[i][nt][h2 * 2 + 1] + b1v;
                if (ADDC) {
                    float2 cv = *(const float2*)(Cb + (size_t)m * 128 + c);
                    x0 += cv.x; x1 += cv.y;
                }
                if (ACT == 1) { x0 = siluf(x0); x1 = siluf(x1); }
                if (ACT == 2) { x0 = fmaxf(x0, 0.f); x1 = fmaxf(x1, 0.f); }
                float* yp = Y + (size_t)m * ldy + c;
                if (RESID) { float2 o = *(const float2*)yp; x0 += o.x; x1 += o.y; }
                float2 o; o.x = x0; o.y = x1;
                *(float2*)yp = o;
            }
        }
    }
}

// ---------------- fused edge layer (multi-tile, W2 staged once) ----------------
#define TILE_E 64
#define EDGE_TILES 8
#define N_TILES (N_EDGES / TILE_E)        // 12500
#define OFF_W2S   0                    // [128][136]
#define OFF_HID   (128*136)            // [64][132]
#define OFF_WR    (OFF_HID + 64*132)
#define OFF_WE    (OFF_WR + 128)
#define OFF_B1    (OFF_WE + 128)
#define OFF_ATT   (OFF_B1 + 128)
#define OFF_B2    (OFF_ATT + 128)
#define OFF_RAD   (OFF_B2 + 128)
#define OFF_EA    (OFF_RAD + 64)
#define OFF_GATE  (OFF_EA + 64)
#define OFF_ROWS  (OFF_GATE + 64)
#define OFF_COLS  (OFF_ROWS + 64)
#define EDGE_SMEM ((OFF_COLS + 64) * 4)

__global__ __launch_bounds__(256) void edge_kernel(
        const float* __restrict__ P, const float* __restrict__ Q,
        const float* __restrict__ radial, const float* __restrict__ ea,
        const int* __restrict__ ei,
        const float* __restrict__ wr, const float* __restrict__ we,
        const float* __restrict__ b1,
        const float* __restrict__ W2, const float* __restrict__ B2,
        const float* __restrict__ attw, const float* __restrict__ attb,
        float* __restrict__ agg) {
    extern __shared__ float sm[];
    float* W2s  = sm + OFF_W2S;
    float* hid  = sm + OFF_HID;
    float* wr_s = sm + OFF_WR;
    float* we_s = sm + OFF_WE;
    float* b1_s = sm + OFF_B1;
    float* at_s = sm + OFF_ATT;
    float* b2_s = sm + OFF_B2;
    float* rd_s = sm + OFF_RAD;
    float* ea_s = sm + OFF_EA;
    float* gt_s = sm + OFF_GATE;
    int* rows_s = (int*)(sm + OFF_ROWS);
    int* cols_s = (int*)(sm + OFF_COLS);

    int t = threadIdx.x;
    int w = t >> 5, lane = t & 31;
    int g = lane >> 2, t4 = lane & 3;
    int eg0 = (w & 3) * 16, ng0 = (w >> 2) * 64;
    float attbv = attb[0];

    // stage constants + W2 once per block
    for (int idx = t; idx < 5 * 128; idx += 256) {
        int a = idx >> 7, c = idx & 127;
        float v;
        if (a == 0) v = wr[c];
        else if (a == 1) v = we[c];
        else if (a == 2) v = b1[c];
        else if (a == 3) v = attw[c];
        else v = B2[c];
        sm[OFF_WR + a * 128 + c] = v;
    }
    for (int idx = t; idx < 128 * 32; idx += 256) {
        int kk = idx >> 5, c4 = (idx & 31) * 4;
        *(float4*)&W2s[kk * 136 + c4] = *(const float4*)(W2 + (size_t)kk * 128 + c4);
    }

    for (int tt = 0; tt < EDGE_TILES; tt++) {
        int tile = blockIdx.x * EDGE_TILES + tt;
        if (tile >= N_TILES) break;
        int e0 = tile * TILE_E;

        __syncthreads();   // prior tile fully consumed smem
        if (t < TILE_E) {
            rows_s[t] = ei[e0 + t];
            rd_s[t] = radial[e0 + t];
            ea_s[t] = ea[e0 + t];
        } else if (t < 2 * TILE_E) {
            cols_s[t - TILE_E] = ei[N_EDGES + e0 + (t - TILE_E)];
        }
        __syncthreads();

        // hid = silu(P[row]+Q[col]+rad*wr+ea*we+b1)
#pragma unroll
        for (int i = 0; i < 8; i++) {
            int idx = t + i * 256;
            int e = idx >> 5, c4 = (idx & 31) * 4;
            float4 p = *(const float4*)(P + (size_t)rows_s[e] * 128 + c4);
            float4 q = *(const float4*)(Q + (size_t)cols_s[e] * 128 + c4);
            float rd = rd_s[e], eav = ea_s[e];
            float4 o;
            o.x = siluf(p.x + q.x + rd * wr_s[c4 + 0] + eav * we_s[c4 + 0] + b1_s[c4 + 0]);
            o.y = siluf(p.y + q.y + rd * wr_s[c4 + 1] + eav * we_s[c4 + 1] + b1_s[c4 + 1]);
            o.z = siluf(p.z + q.z + rd * wr_s[c4 + 2] + eav * we_s[c4 + 2] + b1_s[c4 + 2]);
            o.w = siluf(p.w + q.w + rd * wr_s[c4 + 3] + eav * we_s[c4 + 3] + b1_s[c4 + 3]);
            *(float4*)&hid[e * 132 + c4] = o;
        }
        __syncthreads();

        float acc[8][4];
#pragma unroll
        for (int nt = 0; nt < 8; nt++) { acc[nt][0] = acc[nt][1] = acc[nt][2] = acc[nt][3] = 0.f; }
#pragma unroll
        for (int k0 = 0; k0 < 128; k0 += 8) {
            uint32_t a[4];
            a[0] = f2u(hid[(eg0 + g) * 132 + k0 + t4]);
            a[1] = f2u(hid[(eg0 + g + 8) * 132 + k0 + t4]);
            a[2] = f2u(hid[(eg0 + g) * 132 + k0 + t4 + 4]);
            a[3] = f2u(hid[(eg0 + g + 8) * 132 + k0 + t4 + 4]);
#pragma unroll
            for (int nt = 0; nt < 8; nt++) {
                uint32_t b0 = f2u(W2s[(k0 + t4) * 136 + ng0 + nt * 8 + g]);
                uint32_t b1v = f2u(W2s[(k0 + t4 + 4) * 136 + ng0 + nt * 8 + g]);
                MMA8(acc[nt], a, b0, b1v);
            }
        }
        __syncthreads();   // all hid reads done; reuse as ms

#pragma unroll
        for (int nt = 0; nt < 8; nt++) {
            int c0 = ng0 + nt * 8 + 2 * t4;
            int r0 = eg0 + g, r1 = r0 + 8;
            hid[r0 * 132 + c0]     = siluf(acc[nt][0] + b2_s[c0]);
            hid[r0 * 132 + c0 + 1] = siluf(acc[nt][1] + b2_s[c0 + 1]);
            hid[r1 * 132 + c0]     = siluf(acc[nt][2] + b2_s[c0]);
            hid[r1 * 132 + c0 + 1] = siluf(acc[nt][3] + b2_s[c0 + 1]);
        }
        __syncthreads();

        {
            int e = t >> 2, l4 = t & 3;
            float s = 0.f;
#pragma unroll
            for (int c = l4; c < 128; c += 4) s += hid[e * 132 + c] * at_s[c];
            s += __shfl_down_sync(0xffffffffu, s, 2, 4);
            s += __shfl_down_sync(0xffffffffu, s, 1, 4);
            if (l4 == 0) gt_s[e] = sigmf(s + attbv);
        }
        __syncthreads();

#pragma unroll
        for (int i = 0; i < 8; i++) {
            int idx = t + i * 256;
            int e = idx >> 5, c4 = (idx & 31) * 4;
            float gt = gt_s[e];
            float4 m4 = *(const float4*)&hid[e * 132 + c4];
            float* ptr = agg + (size_t)rows_s[e] * 128 + c4;
            asm volatile("red.global.add.v4.f32 [%0], {%1,%2,%3,%4};"
                         :: "l"(ptr), "f"(m4.x * gt), "f"(m4.y * gt),
                            "f"(m4.z * gt), "f"(m4.w * gt) : "memory");
        }
    }
}

// ---------------- final head ----------------
__global__ void last2_kernel(const float* __restrict__ X, const float* __restrict__ w,
                             const float* __restrict__ b, float* __restrict__ out) {
    int gt = blockIdx.x * blockDim.x + threadIdx.x;
    int n = gt >> 5, lane = gt & 31;
    if (n >= N_NODES) return;
    float s = 0.f;
    for (int c = lane; c < 192; c += 32) s += X[(size_t)n * 192 + c] * w[c];
#pragma unroll
    for (int o = 16; o; o >>= 1) s += __shfl_down_sync(0xffffffffu, s, o);
    if (lane == 0) out[n] = sigmf(s + b[0]);
}

// ---------------- launch ----------------
extern "C" void kernel_launch(void* const* d_in, const int* in_sizes, int n_in,
                              void* d_out, int out_size) {
    const float* node_attrs = (const float*)d_in[0];
    const float* coords     = (const float*)d_in[1];
    const int*   ei         = (const int*)d_in[2];
    const float* ea         = (const float*)d_in[3];
    const float* emb_w  = (const float*)d_in[4];
    const float* emb_b  = (const float*)d_in[5];
    const float* edge_w1 = (const float*)d_in[6];
    const float* edge_b1 = (const float*)d_in[7];
    const float* edge_w2 = (const float*)d_in[8];
    const float* edge_b2 = (const float*)d_in[9];
    const float* att_w   = (const float*)d_in[10];
    const float* att_b   = (const float*)d_in[11];
    const float* node_w1 = (const float*)d_in[12];
    const float* node_b1 = (const float*)d_in[13];
    const float* node_w2 = (const float*)d_in[14];
    const float* node_b2 = (const float*)d_in[15];
    const float* dec_w1  = (const float*)d_in[16];
    const float* dec_b1  = (const float*)d_in[17];
    const float* dec_w2  = (const float*)d_in[18];
    const float* dec_b2  = (const float*)d_in[19];
    const float* ffnn_w1 = (const float*)d_in[20];
    const float* ffnn_b1 = (const float*)d_in[21];
    const float* ffnn_w2 = (const float*)d_in[22];
    const float* ffnn_b2 = (const float*)d_in[23];
    const float* last_w1 = (const float*)d_in[24];
    const float* last_b1 = (const float*)d_in[25];
    const float* last_w2 = (const float*)d_in[26];
    const float* last_b2 = (const float*)d_in[27];

    float *h, *P, *Q, *agg, *tmp, *C, *esmin, *h0p, *esm1, *cat, *last, *radial;
    cudaGetSymbolAddress((void**)&h, g_h);
    cudaGetSymbolAddress((void**)&P, g_P);
    cudaGetSymbolAddress((void**)&Q, g_Q);
    cudaGetSymbolAddress((void**)&agg, g_agg);
    cudaGetSymbolAddress((void**)&tmp, g_tmp);
    cudaGetSymbolAddress((void**)&C, g_C);
    cudaGetSymbolAddress((void**)&esmin, g_esmin);
    cudaGetSymbolAddress((void**)&h0p, g_h0p);
    cudaGetSymbolAddress((void**)&esm1, g_esm1);
    cudaGetSymbolAddress((void**)&cat, g_cat);
    cudaGetSymbolAddress((void**)&last, g_last);
    cudaGetSymbolAddress((void**)&radial, g_radial);

    cudaFuncSetAttribute(edge_kernel, cudaFuncAttributeMaxDynamicSharedMemorySize, EDGE_SMEM);
    cudaFuncSetAttribute(gemm_tc<0, false, true, false, false>,  cudaFuncAttributeMaxDynamicSharedMemorySize, GEMM_SMEM);
    cudaFuncSetAttribute(gemm_tc<2, false, true, false, false>,  cudaFuncAttributeMaxDynamicSharedMemorySize, GEMM_SMEM);
    cudaFuncSetAttribute(gemm_tc<0, false, false, false, false>, cudaFuncAttributeMaxDynamicSharedMemorySize, GEMM_SMEM);
    cudaFuncSetAttribute(gemm_tc<1, false, false, true, true>,   cudaFuncAttributeMaxDynamicSharedMemorySize, GEMM_SMEM);
    cudaFuncSetAttribute(gemm_tc<0, true, true, false, false>,   cudaFuncAttributeMaxDynamicSharedMemorySize, GEMM_SMEM);
    cudaFuncSetAttribute(gemm_tc<1, false, true, false, false>,  cudaFuncAttributeMaxDynamicSharedMemorySize, GEMM_SMEM);

    const int GBM = (N_NODES + 127) / 128;   // 391
    const int EGB = (N_TILES + EDGE_TILES - 1) / EDGE_TILES;   // 1563

    radial_kernel<<<(N_EDGES + 255) / 256, 256>>>(coords, ei, radial);
    copy_inputs<<<N_NODES, 256>>>(node_attrs, esmin, h0p);

    // h = h0 @ emb_w + emb_b   (K=96 padded, KW=83)
    gemm_tc<0, false, true, false, false><<<dim3(GBM, 1), 256, GEMM_SMEM>>>(
        h0p, nullptr, H0P, emb_w, emb_b, nullptr, h, 128, N_NODES, H0P, F_STRUCT, 128);
    // ESM branch -> cat[:,128:192]
    gemm_tc<2, false, true, false, false><<<dim3(GBM, 2), 256, GEMM_SMEM>>>(
        esmin, nullptr, F_ESM, ffnn_w1, ffnn_b1, nullptr, esm1, 256, N_NODES, F_ESM, F_ESM, 256);
    gemm_tc<2, false, true, false, false><<<dim3(GBM, 1), 256, GEMM_SMEM>>>(
        esm1, nullptr, 256, ffnn_w2, ffnn_b2, nullptr, cat + 128, 192, N_NODES, 256, 256, 64);

    for (int i = 0; i < NLAYERS; i++) {
        const float* W1 = edge_w1 + (size_t)i * 258 * 128;
        const float* Wn = node_w1 + (size_t)i * NODE_IN * 128;
        gemm_tc<0, false, false, false, false><<<dim3(GBM, 1), 256, GEMM_SMEM>>>(
            h, nullptr, 128, W1, nullptr, nullptr, P, 128, N_NODES, 128, 128, 128);
        gemm_tc<0, false, false, false, false><<<dim3(GBM, 1), 256, GEMM_SMEM>>>(
            h, nullptr, 128, W1 + 128 * 128, nullptr, nullptr, Q, 128, N_NODES, 128, 128, 128);
        cudaMemsetAsync(agg, 0, (size_t)N_NODES * 128 * sizeof(float));
        edge_kernel<<<EGB, 256, EDGE_SMEM>>>(P, Q, radial, ea, ei,
                                             W1 + 256 * 128, W1 + 257 * 128,
                                             edge_b1 + (size_t)i * 128,
                                             edge_w2 + (size_t)i * 128 * 128,
                                             edge_b2 + (size_t)i * 128,
                                             att_w + (size_t)i * 128,
                                             att_b + i, agg);
        // C = h0p @ Wn[256:339] + node_b1   (h0 contribution of node MLP)
        gemm_tc<0, false, true, false, false><<<dim3(GBM, 1), 256, GEMM_SMEM>>>(
            h0p, nullptr, H0P, Wn + 256 * 128, node_b1 + (size_t)i * 128, nullptr,
            C, 128, N_NODES, H0P, F_STRUCT, 128);
        // tmp = silu(h @ Wn[0:128] + agg @ Wn[128:256] + C)
        gemm_tc<1, false, false, true, true><<<dim3(GBM, 1), 256, GEMM_SMEM>>>(
            h, agg, 128, Wn, nullptr, C, tmp, 128, N_NODES, 256, 256, 128);
        gemm_tc<0, true, true, false, false><<<dim3(GBM, 1), 256, GEMM_SMEM>>>(
            tmp, nullptr, 128, node_w2 + (size_t)i * 128 * 128,
            node_b2 + (size_t)i * 128, nullptr, h, 128, N_NODES, 128, 128, 128);
    }

    // decoder -> cat[:,0:128]
    gemm_tc<1, false, true, false, false><<<dim3(GBM, 1), 256, GEMM_SMEM>>>(
        h, nullptr, 128, dec_w1, dec_b1, nullptr, tmp, 128, N_NODES, 128, 128, 128);
    gemm_tc<0, false, true, false, false><<<dim3(GBM, 1), 256, GEMM_SMEM>>>(
        tmp, nullptr, 128, dec_w2, dec_b2, nullptr, cat, 192, N_NODES, 128, 128, 128);

    // final head
    gemm_tc<1, false, true, false, false><<<dim3(GBM, 2), 256, GEMM_SMEM>>>(
        cat, nullptr, 192, last_w1, last_b1, nullptr, last, 192, N_NODES, 192, 192, 192);
    last2_kernel<<<(N_NODES * 32 + 255) / 256, 256>>>(last, last_w2, last_b2, (float*)d_out);
}